// round 13
// baseline (speedup 1.0000x reference)
#include <cuda_runtime.h>
#include <cuda_bf16.h>
#include <math.h>
#include <stdint.h>

#define S 4096
#define D 1024
#define H 16
#define DH 64
#define F 4096
#define N1 7168              // F + 3*D : fused MLP-in + QKV output width
#define K2 5120              // F + D   : packed activation width [h | o]
#define EPSF 1e-6f

// ---------------- scratch (device globals: alloc-free) ----------------
__device__ float g_q [S * D];
__device__ float g_k [S * D];
__device__ float g_v [S * D];

__device__ __nv_bfloat16 g_xnh[S * D], g_xnl[S * D];       // LN output planes
__device__ __nv_bfloat16 g_acth[S * K2], g_actl[S * K2];   // [h | o] planes, stride K2
__device__ __nv_bfloat16 g_qsh[S * D], g_qsl[S * D];       // q * 1/8 planes
__device__ __nv_bfloat16 g_ksh[S * D], g_ksl[S * D];       // k planes
__device__ __nv_bfloat16 g_vth[D * S], g_vtl[D * S];       // V^T planes [H*64 dims][S keys]
__device__ __nv_bfloat16 g_w1h[N1 * D], g_w1l[N1 * D];     // [w_in|wq|wk|wv]^T  [7168][1024]
__device__ __nv_bfloat16 g_w2h[D * K2], g_w2l[D * K2];     // [w_mo;w_ao]^T      [1024][5120]

// ---------------- small asm helpers (base sm_103 instructions) ----------------
__device__ __forceinline__ uint32_t smem_u32(const void* p) {
    uint32_t a;
    asm("{ .reg .u64 t; cvta.to.shared.u64 t, %1; cvt.u32.u64 %0, t; }" : "=r"(a) : "l"(p));
    return a;
}
__device__ __forceinline__ void cp16(uint32_t d, const void* s) {
    asm volatile("cp.async.cg.shared.global [%0], [%1], 16;" :: "r"(d), "l"(s));
}
#define CP_COMMIT() asm volatile("cp.async.commit_group;" ::: "memory")
#define CP_WAIT1()  asm volatile("cp.async.wait_group 1;" ::: "memory")
#define CP_WAIT0()  asm volatile("cp.async.wait_group 0;" ::: "memory")

__device__ __forceinline__ void ldmx4(uint32_t* r, uint32_t a) {
    asm volatile("ldmatrix.sync.aligned.m8n8.x4.shared.b16 {%0,%1,%2,%3}, [%4];"
                 : "=r"(r[0]), "=r"(r[1]), "=r"(r[2]), "=r"(r[3]) : "r"(a));
}
__device__ __forceinline__ void ldmx2(uint32_t* r, uint32_t a) {
    asm volatile("ldmatrix.sync.aligned.m8n8.x2.shared.b16 {%0,%1}, [%2];"
                 : "=r"(r[0]), "=r"(r[1]) : "r"(a));
}
__device__ __forceinline__ void mma16816(float* c, const uint32_t* a, const uint32_t* b) {
    asm volatile("mma.sync.aligned.m16n8k16.row.col.f32.bf16.bf16.f32 "
                 "{%0,%1,%2,%3}, {%4,%5,%6,%7}, {%8,%9}, {%0,%1,%2,%3};"
                 : "+f"(c[0]), "+f"(c[1]), "+f"(c[2]), "+f"(c[3])
                 : "r"(a[0]), "r"(a[1]), "r"(a[2]), "r"(a[3]), "r"(b[0]), "r"(b[1]));
}

__device__ __forceinline__ float gelu_f(float x) {
    float x3 = x * x * x;
    return 0.5f * x * (1.f + tanhf(0.7978845608028654f * (x + 0.044715f * x3)));
}

__device__ __forceinline__ void packsplit(uint32_t& hi, uint32_t& lo, float a, float b) {
    __nv_bfloat162 h = __floats2bfloat162_rn(a, b);
    float r0 = a - __bfloat162float(__low2bfloat16(h));
    float r1 = b - __bfloat162float(__high2bfloat16(h));
    __nv_bfloat162 l = __floats2bfloat162_rn(r0, r1);
    hi = *reinterpret_cast<uint32_t*>(&h);
    lo = *reinterpret_cast<uint32_t*>(&l);
}

// ---------------- split-transpose: in [Kd][Nd] fp32 -> out[n*ostride + k] bf16 hi/lo ----------------
__global__ void splitT_kernel(const float* __restrict__ in,
                              __nv_bfloat16* __restrict__ hi,
                              __nv_bfloat16* __restrict__ lo,
                              int Kd, int Nd, int ostride) {
    __shared__ float t[32][33];
    int n0 = blockIdx.x * 32, k0 = blockIdx.y * 32;
    int tx = threadIdx.x, ty = threadIdx.y;
#pragma unroll
    for (int j = 0; j < 4; j++)
        t[ty + j * 8][tx] = in[(size_t)(k0 + ty + j * 8) * Nd + n0 + tx];
    __syncthreads();
#pragma unroll
    for (int j = 0; j < 4; j++) {
        float v = t[tx][ty + j * 8];
        int n = n0 + ty + j * 8, k = k0 + tx;
        __nv_bfloat16 h = __float2bfloat16(v);
        hi[(size_t)n * ostride + k] = h;
        lo[(size_t)n * ostride + k] = __float2bfloat16(v - __bfloat162float(h));
    }
}

// ---------------- LayerNorm + split ----------------
__global__ void ln_split_kernel(const float* __restrict__ x,
                                const float* __restrict__ gamma,
                                const float* __restrict__ beta,
                                uint32_t* __restrict__ yh,
                                uint32_t* __restrict__ yl) {
    __shared__ float sh[8];
    __shared__ float stat;
    int row = blockIdx.x;
    int t = threadIdx.x;
    float4 xv = ((const float4*)(x + (size_t)row * D))[t];

    float s = xv.x + xv.y + xv.z + xv.w;
#pragma unroll
    for (int o = 16; o > 0; o >>= 1) s += __shfl_xor_sync(0xffffffffu, s, o);
    if ((t & 31) == 0) sh[t >> 5] = s;
    __syncthreads();
    if (t == 0) {
        float tot = 0.f;
#pragma unroll
        for (int i = 0; i < 8; i++) tot += sh[i];
        stat = tot * (1.f / (float)D);
    }
    __syncthreads();
    float mean = stat;

    float d0 = xv.x - mean, d1 = xv.y - mean, d2 = xv.z - mean, d3 = xv.w - mean;
    float sq = d0 * d0 + d1 * d1 + d2 * d2 + d3 * d3;
#pragma unroll
    for (int o = 16; o > 0; o >>= 1) sq += __shfl_xor_sync(0xffffffffu, sq, o);
    __syncthreads();
    if ((t & 31) == 0) sh[t >> 5] = sq;
    __syncthreads();
    if (t == 0) {
        float tot = 0.f;
#pragma unroll
        for (int i = 0; i < 8; i++) tot += sh[i];
        stat = rsqrtf(tot * (1.f / (float)D) + EPSF);
    }
    __syncthreads();
    float rinv = stat;

    float4 gv = ((const float4*)gamma)[t];
    float4 bv = ((const float4*)beta)[t];
    float v0 = d0 * rinv * gv.x + bv.x;
    float v1 = d1 * rinv * gv.y + bv.y;
    float v2 = d2 * rinv * gv.z + bv.z;
    float v3 = d3 * rinv * gv.w + bv.w;
    uint32_t h0, l0, h1, l1;
    packsplit(h0, l0, v0, v1);
    packsplit(h1, l1, v2, v3);
    int idx = row * (D / 2) + 2 * t;
    yh[idx] = h0; yh[idx + 1] = h1;
    yl[idx] = l0; yl[idx + 1] = l1;
}

// ---------------- per-head LN + scale + split ----------------
__global__ void qknorm_split(const float* __restrict__ tq, const float* __restrict__ scale,
                             uint32_t* __restrict__ oh, uint32_t* __restrict__ ol, float sc) {
    int row = blockIdx.x * blockDim.x + threadIdx.x;
    const float* p = tq + (size_t)row * DH;
    float4 v[16];
    float s = 0.f;
#pragma unroll
    for (int i = 0; i < 16; i++) {
        v[i] = ((const float4*)p)[i];
        s += v[i].x + v[i].y + v[i].z + v[i].w;
    }
    float mean = s * (1.f / (float)DH);
    float sq = 0.f;
#pragma unroll
    for (int i = 0; i < 16; i++) {
        v[i].x -= mean; v[i].y -= mean; v[i].z -= mean; v[i].w -= mean;
        sq += v[i].x * v[i].x + v[i].y * v[i].y + v[i].z * v[i].z + v[i].w * v[i].w;
    }
    float r = rsqrtf(sq * (1.f / (float)DH) + EPSF) * sc;
#pragma unroll
    for (int i = 0; i < 16; i++) {
        float4 scv = ((const float4*)scale)[i];
        uint32_t h0, l0, h1, l1;
        packsplit(h0, l0, v[i].x * r * scv.x, v[i].y * r * scv.y);
        packsplit(h1, l1, v[i].z * r * scv.z, v[i].w * r * scv.w);
        int idx = row * (DH / 2) + 2 * i;
        oh[idx] = h0; oh[idx + 1] = h1;
        ol[idx] = l0; ol[idx + 1] = l1;
    }
}

// ================= HMMA GEMM core (round-9 proven mainloop) =================
#define GBM 128
#define GBN 128
#define GBK 32
#define PLANE_B (128 * 40 * 2)        // 10240 B per plane (128 rows x 80 B stride)
#define BUF_B   (4 * PLANE_B)         // Ah, Al, Bh, Bl
#define GSMEM   (2 * BUF_B)           // 81920 B, 2 CTAs/SM

__device__ __forceinline__ void issue_chunk(
    uint32_t base,
    const __nv_bfloat16* Ah, const __nv_bfloat16* Al,
    const __nv_bfloat16* Bh, const __nv_bfloat16* Bl,
    int bm, int bn, int kc, int lda, int ldb, int tid)
{
    int row  = tid >> 1;
    int half = tid & 1;
    uint32_t doff = row * 80 + half * 32;
    size_t aoff = (size_t)(bm + row) * lda + kc + half * 16;
    size_t boff = (size_t)(bn + row) * ldb + kc + half * 16;
    cp16(base + doff,                    Ah + aoff);
    cp16(base + doff + 16,               Ah + aoff + 8);
    cp16(base + PLANE_B + doff,          Al + aoff);
    cp16(base + PLANE_B + doff + 16,     Al + aoff + 8);
    cp16(base + 2 * PLANE_B + doff,      Bh + boff);
    cp16(base + 2 * PLANE_B + doff + 16, Bh + boff + 8);
    cp16(base + 3 * PLANE_B + doff,      Bl + boff);
    cp16(base + 3 * PLANE_B + doff + 16, Bl + boff + 8);
}

__device__ __forceinline__ void hmma_mainloop(
    uint32_t sb, float acc[4][4][4],
    const __nv_bfloat16* Ah, const __nv_bfloat16* Al,
    const __nv_bfloat16* Bh, const __nv_bfloat16* Bl,
    int bm, int bn, int K, int lda, int ldb, int tid, int lane, int wm, int wn)
{
    uint32_t a_off = (uint32_t)((wm * 64 + (lane & 7) + (lane & 8)) * 80 + ((lane >> 4) << 4));
    uint32_t b_off = (uint32_t)((wn * 32 + (lane & 7)) * 80 + ((lane & 8) << 1));

    int nk = K / GBK;
    issue_chunk(sb, Ah, Al, Bh, Bl, bm, bn, 0, lda, ldb, tid);
    CP_COMMIT();

    for (int c = 0; c < nk; c++) {
        CP_WAIT0();
        __syncthreads();
        if (c + 1 < nk) {
            issue_chunk(sb + ((c + 1) & 1) * BUF_B, Ah, Al, Bh, Bl, bm, bn, (c + 1) * GBK, lda, ldb, tid);
            CP_COMMIT();
        }
        uint32_t base = sb + (c & 1) * BUF_B;
        uint32_t aH = base, aL = base + PLANE_B;
        uint32_t bH = base + 2 * PLANE_B, bL = base + 3 * PLANE_B;

#pragma unroll
        for (int k16 = 0; k16 < 2; k16++) {
            uint32_t kb = k16 * 32;
            uint32_t ahf[4][4], bfr[4][2];
#pragma unroll
            for (int mt = 0; mt < 4; mt++) ldmx4(ahf[mt], aH + a_off + mt * 1280 + kb);
#pragma unroll
            for (int nt = 0; nt < 4; nt++) ldmx2(bfr[nt], bH + b_off + nt * 640 + kb);
#pragma unroll
            for (int mt = 0; mt < 4; mt++)
#pragma unroll
                for (int nt = 0; nt < 4; nt++) mma16816(acc[mt][nt], ahf[mt], bfr[nt]);

            uint32_t alf[4][4];
#pragma unroll
            for (int mt = 0; mt < 4; mt++) ldmx4(alf[mt], aL + a_off + mt * 1280 + kb);
#pragma unroll
            for (int mt = 0; mt < 4; mt++)
#pragma unroll
                for (int nt = 0; nt < 4; nt++) mma16816(acc[mt][nt], alf[mt], bfr[nt]);

#pragma unroll
            for (int nt = 0; nt < 4; nt++) ldmx2(bfr[nt], bL + b_off + nt * 640 + kb);
#pragma unroll
            for (int mt = 0; mt < 4; mt++)
#pragma unroll
                for (int nt = 0; nt < 4; nt++) mma16816(acc[mt][nt], ahf[mt], bfr[nt]);
        }
    }
}

// ---- fused GEMM 1: [xn] @ [w_in|wq|wk|wv]^T over N=7168 ----
__global__ void __launch_bounds__(256, 2) hmma_gemm_f1(
    const __nv_bfloat16* __restrict__ Ah, const __nv_bfloat16* __restrict__ Al,
    const __nv_bfloat16* __restrict__ Bh, const __nv_bfloat16* __restrict__ Bl,
    const float* __restrict__ b_in, const float* __restrict__ bq,
    const float* __restrict__ bk, const float* __restrict__ bv,
    uint32_t* __restrict__ acth, uint32_t* __restrict__ actl,
    float* __restrict__ qf, float* __restrict__ kf, float* __restrict__ vf)
{
    extern __shared__ __align__(128) char smem[];
    uint32_t sb = smem_u32(smem);
    int tid = threadIdx.x, lane = tid & 31, wid = tid >> 5;
    int wm = wid >> 2, wn = wid & 3;
    int bm = blockIdx.y * GBM, bn = blockIdx.x * GBN;

    float acc[4][4][4];
#pragma unroll
    for (int i = 0; i < 4; i++)
#pragma unroll
        for (int j = 0; j < 4; j++)
#pragma unroll
            for (int r = 0; r < 4; r++) acc[i][j][r] = 0.f;

    hmma_mainloop(sb, acc, Ah, Al, Bh, Bl, bm, bn, D, D, D, tid, lane, wm, wn);

    int lr = lane >> 2, lc = (lane & 3) * 2;
#pragma unroll
    for (int mt = 0; mt < 4; mt++) {
#pragma unroll
        for (int nt = 0; nt < 4; nt++) {
            float* a = acc[mt][nt];
            int m0 = bm + wm * 64 + mt * 16 + lr;
            int n0 = bn + wn * 32 + nt * 8 + lc;
            if (n0 < F) {
                float b0 = b_in[n0], b1 = b_in[n0 + 1];
                float v0 = gelu_f(a[0] + b0), v1 = gelu_f(a[1] + b1);
                float v2 = gelu_f(a[2] + b0), v3 = gelu_f(a[3] + b1);
                uint32_t h0, l0, h1, l1;
                packsplit(h0, l0, v0, v1);
                packsplit(h1, l1, v2, v3);
                size_t i0 = (size_t)m0 * (K2 / 2) + (n0 >> 1);
                size_t i1 = (size_t)(m0 + 8) * (K2 / 2) + (n0 >> 1);
                acth[i0] = h0; actl[i0] = l0;
                acth[i1] = h1; actl[i1] = l1;
            } else {
                int r = (n0 - F) >> 10;
                int c = (n0 - F) & (D - 1);
                const float* bp = (r == 0) ? bq : (r == 1) ? bk : bv;
                float* dst = (r == 0) ? qf : (r == 1) ? kf : vf;
                float b0 = bp[c], b1 = bp[c + 1];
                float2 w0 = {a[0] + b0, a[1] + b1};
                float2 w1 = {a[2] + b0, a[3] + b1};
                *(float2*)(dst + (size_t)m0 * D + c) = w0;
                *(float2*)(dst + (size_t)(m0 + 8) * D + c) = w1;
            }
        }
    }
}

// ---- accumulate GEMM: C += A @ B^T over K window (strided; caller applies row offsets via pointers) ----
__global__ void __launch_bounds__(256, 2) hmma_gemm_acc(
    const __nv_bfloat16* __restrict__ Ah, const __nv_bfloat16* __restrict__ Al,
    const __nv_bfloat16* __restrict__ Bh, const __nv_bfloat16* __restrict__ Bl,
    float* __restrict__ C, int N, int K, int lda, int ldb)
{
    extern __shared__ __align__(128) char smem[];
    uint32_t sb = smem_u32(smem);
    int tid = threadIdx.x, lane = tid & 31, wid = tid >> 5;
    int wm = wid >> 2, wn = wid & 3;
    int bm = blockIdx.y * GBM, bn = blockIdx.x * GBN;

    float acc[4][4][4];
#pragma unroll
    for (int i = 0; i < 4; i++)
#pragma unroll
        for (int j = 0; j < 4; j++)
#pragma unroll
            for (int r = 0; r < 4; r++) acc[i][j][r] = 0.f;

    hmma_mainloop(sb, acc, Ah, Al, Bh, Bl, bm, bn, K, lda, ldb, tid, lane, wm, wn);

    int lr = lane >> 2, lc = (lane & 3) * 2;
#pragma unroll
    for (int mt = 0; mt < 4; mt++) {
#pragma unroll
        for (int nt = 0; nt < 4; nt++) {
            float* a = acc[mt][nt];
            int m0 = bm + wm * 64 + mt * 16 + lr;
            int n0 = bn + wn * 32 + nt * 8 + lc;
            float2* p0 = (float2*)(C + (size_t)m0 * N + n0);
            float2* p1 = (float2*)(C + (size_t)(m0 + 8) * N + n0);
            float2 v0 = *p0, v1 = *p1;
            v0.x += a[0]; v0.y += a[1];
            v1.x += a[2]; v1.y += a[3];
            *p0 = v0; *p1 = v1;
        }
    }
}

// ================= HMMA flash attention (round-9 body + qt_base) =================
#define AT_STRIDE 144
#define AT_PLANE (64 * AT_STRIDE)
#define AT_BUF   (4 * AT_PLANE)
#define AT_QOFF  (2 * AT_BUF)
#define AT_QLO   (128 * AT_STRIDE)
#define AT_SMEM  (2 * AT_BUF + 2 * 128 * AT_STRIDE)

__device__ __forceinline__ void at_load_tile(
    uint32_t dst, const __nv_bfloat16* kh, const __nv_bfloat16* kl,
    const __nv_bfloat16* vth, const __nv_bfloat16* vtl,
    int head, int kt, int tid)
{
    int row = tid >> 2, q4 = tid & 3;
    size_t koff = (size_t)(kt * 64 + row) * D + head * DH + q4 * 16;
    uint32_t d = dst + row * AT_STRIDE + q4 * 32;
    cp16(d,                    kh + koff);
    cp16(d + 16,               kh + koff + 8);
    cp16(d + AT_PLANE,         kl + koff);
    cp16(d + AT_PLANE + 16,    kl + koff + 8);
    size_t voff = (size_t)(head * DH + row) * S + kt * 64 + q4 * 16;
    cp16(d + 2 * AT_PLANE,      vth + voff);
    cp16(d + 2 * AT_PLANE + 16, vth + voff + 8);
    cp16(d + 3 * AT_PLANE,      vtl + voff);
    cp16(d + 3 * AT_PLANE + 16, vtl + voff + 8);
}

__global__ void __launch_bounds__(256, 2) hmma_attn(
    const __nv_bfloat16* __restrict__ qh, const __nv_bfloat16* __restrict__ ql,
    const __nv_bfloat16* __restrict__ kh, const __nv_bfloat16* __restrict__ kl,
    const __nv_bfloat16* __restrict__ vth, const __nv_bfloat16* __restrict__ vtl,
    uint32_t* __restrict__ acth, uint32_t* __restrict__ actl,
    int qt_base)
{
    extern __shared__ __align__(128) char smem[];
    uint32_t sb = smem_u32(smem);
    int tid = threadIdx.x, lane = tid & 31, wid = tid >> 5;
    int qt = qt_base + (int)gridDim.x - 1 - (int)blockIdx.x;   // heavy tiles first
    int head = blockIdx.y;
    int ntiles = 2 * qt + 2;

    {
        int row = tid >> 1, half = tid & 1;
        const __nv_bfloat16* s0 = qh + (size_t)(qt * 128 + row) * D + head * DH + half * 32;
        const __nv_bfloat16* s1 = ql + (size_t)(qt * 128 + row) * D + head * DH + half * 32;
        uint32_t dq = sb + AT_QOFF + row * AT_STRIDE + half * 64;
        cp16(dq,      s0); cp16(dq + 16, s0 + 8);
        cp16(dq + 32, s0 + 16); cp16(dq + 48, s0 + 24);
        uint32_t dl = dq + AT_QLO;
        cp16(dl,      s1); cp16(dl + 16, s1 + 8);
        cp16(dl + 32, s1 + 16); cp16(dl + 48, s1 + 24);
    }
    CP_COMMIT();
    at_load_tile(sb, kh, kl, vth, vtl, head, 0, tid);
    CP_COMMIT();
    if (ntiles > 1) { at_load_tile(sb + AT_BUF, kh, kl, vth, vtl, head, 1, tid); CP_COMMIT(); }

    float oacc[8][4];
#pragma unroll
    for (int i = 0; i < 8; i++)
#pragma unroll
        for (int j = 0; j < 4; j++) oacc[i][j] = 0.f;
    float m0 = -INFINITY, m1 = -INFINITY, l0 = 0.f, l1 = 0.f;
    int row0 = qt * 128 + wid * 16 + (lane >> 2);
    uint32_t q_base = sb + AT_QOFF + (wid * 16 + (lane & 15)) * AT_STRIDE + ((lane >> 4) & 1) * 16;

    for (int kt = 0; kt < ntiles; kt++) {
        if (kt + 1 < ntiles) CP_WAIT1(); else CP_WAIT0();
        __syncthreads();
        uint32_t base = sb + (kt & 1) * AT_BUF;

        if (kt * 64 <= qt * 128 + wid * 16 + 15) {
            float s[8][4];
#pragma unroll
            for (int i = 0; i < 8; i++)
#pragma unroll
                for (int j = 0; j < 4; j++) s[i][j] = 0.f;

#pragma unroll
            for (int kc = 0; kc < 4; kc++) {
                uint32_t qh_f[4], ql_f[4];
                ldmx4(qh_f, q_base + kc * 32);
                ldmx4(ql_f, q_base + AT_QLO + kc * 32);
                uint32_t koff = ((lane & 8) << 1) + kc * 32;
#pragma unroll
                for (int nt = 0; nt < 8; nt++) {
                    uint32_t ka = base + (nt * 8 + (lane & 7)) * AT_STRIDE + koff;
                    uint32_t bh[2], bl[2];
                    ldmx2(bh, ka);
                    ldmx2(bl, ka + AT_PLANE);
                    mma16816(s[nt], qh_f, bh);
                    mma16816(s[nt], qh_f, bl);
                    mma16816(s[nt], ql_f, bh);
                }
            }

            if (kt >= 2 * qt) {
#pragma unroll
                for (int nt = 0; nt < 8; nt++) {
                    int c = kt * 64 + nt * 8 + 2 * (lane & 3);
                    if (c     > row0)     s[nt][0] = -INFINITY;
                    if (c + 1 > row0)     s[nt][1] = -INFINITY;
                    if (c     > row0 + 8) s[nt][2] = -INFINITY;
                    if (c + 1 > row0 + 8) s[nt][3] = -INFINITY;
                }
            }

            float mx0 = -INFINITY, mx1 = -INFINITY;
#pragma unroll
            for (int nt = 0; nt < 8; nt++) {
                mx0 = fmaxf(mx0, fmaxf(s[nt][0], s[nt][1]));
                mx1 = fmaxf(mx1, fmaxf(s[nt][2], s[nt][3]));
            }
            mx0 = fmaxf(mx0, __shfl_xor_sync(0xffffffffu, mx0, 1));
            mx0 = fmaxf(mx0, __shfl_xor_sync(0xffffffffu, mx0, 2));
            mx1 = fmaxf(mx1, __shfl_xor_sync(0xffffffffu, mx1, 1));
            mx1 = fmaxf(mx1, __shfl_xor_sync(0xffffffffu, mx1, 2));
            float nm0 = fmaxf(m0, mx0), nm1 = fmaxf(m1, mx1);
            float a0 = __expf(m0 - nm0), a1 = __expf(m1 - nm1);
            m0 = nm0; m1 = nm1;
            float ps0 = 0.f, ps1 = 0.f;
#pragma unroll
            for (int nt = 0; nt < 8; nt++) {
                s[nt][0] = __expf(s[nt][0] - m0); ps0 += s[nt][0];
                s[nt][1] = __expf(s[nt][1] - m0); ps0 += s[nt][1];
                s[nt][2] = __expf(s[nt][2] - m1); ps1 += s[nt][2];
                s[nt][3] = __expf(s[nt][3] - m1); ps1 += s[nt][3];
            }
            l0 = l0 * a0 + ps0;
            l1 = l1 * a1 + ps1;
#pragma unroll
            for (int dt = 0; dt < 8; dt++) {
                oacc[dt][0] *= a0; oacc[dt][1] *= a0;
                oacc[dt][2] *= a1; oacc[dt][3] *= a1;
            }

#pragma unroll
            for (int kc = 0; kc < 4; kc++) {
                uint32_t ph[4], pl[4];
                packsplit(ph[0], pl[0], s[2 * kc][0],     s[2 * kc][1]);
                packsplit(ph[1], pl[1], s[2 * kc][2],     s[2 * kc][3]);
                packsplit(ph[2], pl[2], s[2 * kc + 1][0], s[2 * kc + 1][1]);
                packsplit(ph[3], pl[3], s[2 * kc + 1][2], s[2 * kc + 1][3]);
                uint32_t koff = ((lane & 8) << 1) + kc * 32;
#pragma unroll
                for (int dt = 0; dt < 8; dt++) {
                    uint32_t va = base + 2 * AT_PLANE + (dt * 8 + (lane & 7)) * AT_STRIDE + koff;
                    uint32_t vh[2], vl[2];
                    ldmx2(vh, va);
                    ldmx2(vl, va + AT_PLANE);
                    mma16816(oacc[dt], ph, vh);
                    mma16816(oacc[dt], ph, vl);
                    mma16816(oacc[dt], pl, vh);
                }
            }
        }
        __syncthreads();
        if (kt + 2 < ntiles) { at_load_tile(base, kh, kl, vth, vtl, head, kt + 2, tid); CP_COMMIT(); }
    }

    l0 += __shfl_xor_sync(0xffffffffu, l0, 1);
    l0 += __shfl_xor_sync(0xffffffffu, l0, 2);
    l1 += __shfl_xor_sync(0xffffffffu, l1, 1);
    l1 += __shfl_xor_sync(0xffffffffu, l1, 2);
    float i0 = 1.f / l0, i1 = 1.f / l1;
#pragma unroll
    for (int dt = 0; dt < 8; dt++) {
        int col = F + head * DH + dt * 8 + 2 * (lane & 3);
        uint32_t h0, lo0, h1, lo1;
        packsplit(h0, lo0, oacc[dt][0] * i0, oacc[dt][1] * i0);
        packsplit(h1, lo1, oacc[dt][2] * i1, oacc[dt][3] * i1);
        size_t i0x = (size_t)row0 * (K2 / 2) + (col >> 1);
        size_t i1x = (size_t)(row0 + 8) * (K2 / 2) + (col >> 1);
        acth[i0x] = h0; actl[i0x] = lo0;
        acth[i1x] = h1; actl[i1x] = lo1;
    }
}

// ---------------- out = x + b_mo + b_ao ----------------
__global__ void init_out_kernel(const float* __restrict__ x,
                                const float* __restrict__ bmo,
                                const float* __restrict__ bao,
                                float* __restrict__ out) {
    int i = blockIdx.x * blockDim.x + threadIdx.x;
    int col = i & (D - 1);
    out[i] = x[i] + bmo[col] + bao[col];
}

// ---------------- launch (3-stream fork-join graph) ----------------
extern "C" void kernel_launch(void* const* d_in, const int* in_sizes, int n_in,
                              void* d_out, int out_size) {
    const float* x        = (const float*)d_in[0];
    // d_in[1] = mask (causal tril) handled analytically
    const float* ln_scale = (const float*)d_in[2];
    const float* ln_bias  = (const float*)d_in[3];
    const float* w_in     = (const float*)d_in[4];
    const float* b_in     = (const float*)d_in[5];
    const float* wq       = (const float*)d_in[6];
    const float* bq       = (const float*)d_in[7];
    const float* wk       = (const float*)d_in[8];
    const float* bk       = (const float*)d_in[9];
    const float* wv       = (const float*)d_in[10];
    const float* bv       = (const float*)d_in[11];
    const float* qn       = (const float*)d_in[12];
    const float* kn       = (const float*)d_in[13];
    const float* w_mo     = (const float*)d_in[14];
    const float* b_mo     = (const float*)d_in[15];
    const float* w_ao     = (const float*)d_in[16];
    const float* b_ao     = (const float*)d_in[17];
    float* out = (float*)d_out;

    float *q, *k, *v;
    cudaGetSymbolAddress((void**)&q, g_q);
    cudaGetSymbolAddress((void**)&k, g_k);
    cudaGetSymbolAddress((void**)&v, g_v);

    __nv_bfloat16 *xnh, *xnl, *acth, *actl, *qsh, *qsl, *ksh, *ksl, *vth, *vtl;
    __nv_bfloat16 *w1h, *w1l, *w2h, *w2l;
    cudaGetSymbolAddress((void**)&xnh, g_xnh);   cudaGetSymbolAddress((void**)&xnl, g_xnl);
    cudaGetSymbolAddress((void**)&acth, g_acth); cudaGetSymbolAddress((void**)&actl, g_actl);
    cudaGetSymbolAddress((void**)&qsh, g_qsh);   cudaGetSymbolAddress((void**)&qsl, g_qsl);
    cudaGetSymbolAddress((void**)&ksh, g_ksh);   cudaGetSymbolAddress((void**)&ksl, g_ksl);
    cudaGetSymbolAddress((void**)&vth, g_vth);   cudaGetSymbolAddress((void**)&vtl, g_vtl);
    cudaGetSymbolAddress((void**)&w1h, g_w1h);   cudaGetSymbolAddress((void**)&w1l, g_w1l);
    cudaGetSymbolAddress((void**)&w2h, g_w2h);   cudaGetSymbolAddress((void**)&w2l, g_w2l);

    cudaFuncSetAttribute(hmma_gemm_f1,  cudaFuncAttributeMaxDynamicSharedMemorySize, GSMEM);
    cudaFuncSetAttribute(hmma_gemm_acc, cudaFuncAttributeMaxDynamicSharedMemorySize, GSMEM);
    cudaFuncSetAttribute(hmma_attn,     cudaFuncAttributeMaxDynamicSharedMemorySize, AT_SMEM);

    static cudaStream_t side = nullptr, side2 = nullptr;
    static cudaEvent_t ev_fork = nullptr, ev_ln = nullptr, ev_f1 = nullptr,
                       ev_kv = nullptr, ev_mo = nullptr, ev_ahi = nullptr, ev_ohi = nullptr;
    if (!side) {
        cudaStreamCreateWithFlags(&side,  cudaStreamNonBlocking);
        cudaStreamCreateWithFlags(&side2, cudaStreamNonBlocking);
        cudaEventCreateWithFlags(&ev_fork, cudaEventDisableTiming);
        cudaEventCreateWithFlags(&ev_ln,   cudaEventDisableTiming);
        cudaEventCreateWithFlags(&ev_f1,   cudaEventDisableTiming);
        cudaEventCreateWithFlags(&ev_kv,   cudaEventDisableTiming);
        cudaEventCreateWithFlags(&ev_mo,   cudaEventDisableTiming);
        cudaEventCreateWithFlags(&ev_ahi,  cudaEventDisableTiming);
        cudaEventCreateWithFlags(&ev_ohi,  cudaEventDisableTiming);
    }

    cudaEventRecord(ev_fork, 0);
    cudaStreamWaitEvent(side,  ev_fork, 0);
    cudaStreamWaitEvent(side2, ev_fork, 0);

    // side2: LN (depends only on x) — overlaps w1 packing on main
    ln_split_kernel<<<S, 256, 0, side2>>>(x, ln_scale, ln_bias, (uint32_t*)xnh, (uint32_t*)xnl);
    cudaEventRecord(ev_ln, side2);

    // side: w2 packing + out init
    splitT_kernel<<<dim3(D / 32, F / 32), dim3(32, 8), 0, side>>>(w_mo, w2h, w2l, F, D, K2);
    splitT_kernel<<<dim3(D / 32, D / 32), dim3(32, 8), 0, side>>>(w_ao, w2h + F, w2l + F, D, D, K2);
    init_out_kernel<<<(S * D) / 256, 256, 0, side>>>(x, b_mo, b_ao, out);

    // main: w1 packing, then f1 (after LN)
    splitT_kernel<<<dim3(F / 32, D / 32), dim3(32, 8)>>>(w_in, w1h, w1l, D, F, D);
    splitT_kernel<<<dim3(D / 32, D / 32), dim3(32, 8)>>>(wq, w1h + (size_t)F * D, w1l + (size_t)F * D, D, D, D);
    splitT_kernel<<<dim3(D / 32, D / 32), dim3(32, 8)>>>(wk, w1h + (size_t)(F + D) * D, w1l + (size_t)(F + D) * D, D, D, D);
    splitT_kernel<<<dim3(D / 32, D / 32), dim3(32, 8)>>>(wv, w1h + (size_t)(F + 2 * D) * D, w1l + (size_t)(F + 2 * D) * D, D, D, D);
    cudaStreamWaitEvent(0, ev_ln, 0);
    hmma_gemm_f1<<<dim3(N1 / GBN, S / GBM), 256, GSMEM>>>(
        xnh, xnl, w1h, w1l, b_in, bq, bk, bv,
        (uint32_t*)acth, (uint32_t*)actl, q, k, v);
    cudaEventRecord(ev_f1, 0);

    // side: out += h @ w_mo — overlaps attention prep + heavy attention half
    cudaStreamWaitEvent(side, ev_f1, 0);
    hmma_gemm_acc<<<dim3(D / GBN, S / GBM), 256, GSMEM, side>>>(
        acth, actl, w2h, w2l, out, D, F, K2, K2);
    cudaEventRecord(ev_mo, side);

    // side2: qknorm(k) + splitT(v) — overlaps qknorm(q) on main
    cudaStreamWaitEvent(side2, ev_f1, 0);
    qknorm_split<<<(S * H) / 256, 256, 0, side2>>>(k, kn, (uint32_t*)ksh, (uint32_t*)ksl, 1.f);
    splitT_kernel<<<dim3(D / 32, S / 32), dim3(32, 8), 0, side2>>>(v, vth, vtl, S, D, S);
    cudaEventRecord(ev_kv, side2);

    // main: qknorm(q); attention heavy half (qt 16..31), then light half (qt 0..15)
    qknorm_split<<<(S * H) / 256, 256>>>(q, qn, (uint32_t*)qsh, (uint32_t*)qsl, 0.125f);
    cudaStreamWaitEvent(0, ev_kv, 0);
    hmma_attn<<<dim3(16, H), 256, AT_SMEM>>>(qsh, qsl, ksh, ksl, vth, vtl,
                                             (uint32_t*)acth, (uint32_t*)actl, 16);
    cudaEventRecord(ev_ahi, 0);
    hmma_attn<<<dim3(16, H), 256, AT_SMEM>>>(qsh, qsl, ksh, ksl, vth, vtl,
                                             (uint32_t*)acth, (uint32_t*)actl, 0);

    // side: o @ w_ao on rows [2048, 4096) — overlaps light attention half
    cudaStreamWaitEvent(side, ev_ahi, 0);
    hmma_gemm_acc<<<dim3(D / GBN, 16), 256, GSMEM, side>>>(
        acth + F + (size_t)2048 * K2, actl + F + (size_t)2048 * K2,
        w2h + F, w2l + F, out + (size_t)2048 * D, D, D, K2, K2);
    cudaEventRecord(ev_ohi, side);

    // main: o @ w_ao on rows [0, 2048) after light half + h@w_mo complete
    cudaStreamWaitEvent(0, ev_mo, 0);
    hmma_gemm_acc<<<dim3(D / GBN, 16), 256, GSMEM>>>(
        acth + F, actl + F, w2h + F, w2l + F, out, D, D, K2, K2);
    // join: ensure the side o@w_ao half is ordered before graph completion on stream 0
    cudaStreamWaitEvent(0, ev_ohi, 0);
}

// round 14
// speedup vs baseline: 1.6319x; 1.6319x over previous
#include <cuda_runtime.h>
#include <cuda_bf16.h>
#include <math.h>
#include <stdint.h>

#define S 4096
#define D 1024
#define H 16
#define DH 64
#define F 4096
#define N1 7168              // F + 3*D : fused MLP-in + QKV output width
#define K2 5120              // F + D   : packed activation width [h | o]
#define EPSF 1e-6f

// ---------------- scratch (device globals: alloc-free) ----------------
__device__ float g_q [S * D];
__device__ float g_k [S * D];
__device__ float g_v [S * D];

__device__ __nv_bfloat16 g_xnh[S * D], g_xnl[S * D];       // LN output planes
__device__ __nv_bfloat16 g_acth[S * K2], g_actl[S * K2];   // [h | o] planes, stride K2
__device__ __nv_bfloat16 g_qsh[S * D], g_qsl[S * D];       // q * 1/8 planes
__device__ __nv_bfloat16 g_ksh[S * D], g_ksl[S * D];       // k planes
__device__ __nv_bfloat16 g_vth[D * S], g_vtl[D * S];       // V^T planes [H*64 dims][S keys]
__device__ __nv_bfloat16 g_w1h[N1 * D], g_w1l[N1 * D];     // [w_in|wq|wk|wv]^T  [7168][1024]
__device__ __nv_bfloat16 g_w2h[D * K2], g_w2l[D * K2];     // [w_mo;w_ao]^T      [1024][5120]

// ---------------- small asm helpers (base sm_103 instructions) ----------------
__device__ __forceinline__ uint32_t smem_u32(const void* p) {
    uint32_t a;
    asm("{ .reg .u64 t; cvta.to.shared.u64 t, %1; cvt.u32.u64 %0, t; }" : "=r"(a) : "l"(p));
    return a;
}
__device__ __forceinline__ void cp16(uint32_t d, const void* s) {
    asm volatile("cp.async.cg.shared.global [%0], [%1], 16;" :: "r"(d), "l"(s));
}
#define CP_COMMIT() asm volatile("cp.async.commit_group;" ::: "memory")
#define CP_WAIT1()  asm volatile("cp.async.wait_group 1;" ::: "memory")
#define CP_WAIT0()  asm volatile("cp.async.wait_group 0;" ::: "memory")

__device__ __forceinline__ void ldmx4(uint32_t* r, uint32_t a) {
    asm volatile("ldmatrix.sync.aligned.m8n8.x4.shared.b16 {%0,%1,%2,%3}, [%4];"
                 : "=r"(r[0]), "=r"(r[1]), "=r"(r[2]), "=r"(r[3]) : "r"(a));
}
__device__ __forceinline__ void ldmx2(uint32_t* r, uint32_t a) {
    asm volatile("ldmatrix.sync.aligned.m8n8.x2.shared.b16 {%0,%1}, [%2];"
                 : "=r"(r[0]), "=r"(r[1]) : "r"(a));
}
__device__ __forceinline__ void mma16816(float* c, const uint32_t* a, const uint32_t* b) {
    asm volatile("mma.sync.aligned.m16n8k16.row.col.f32.bf16.bf16.f32 "
                 "{%0,%1,%2,%3}, {%4,%5,%6,%7}, {%8,%9}, {%0,%1,%2,%3};"
                 : "+f"(c[0]), "+f"(c[1]), "+f"(c[2]), "+f"(c[3])
                 : "r"(a[0]), "r"(a[1]), "r"(a[2]), "r"(a[3]), "r"(b[0]), "r"(b[1]));
}

__device__ __forceinline__ float gelu_f(float x) {
    float x3 = x * x * x;
    return 0.5f * x * (1.f + tanhf(0.7978845608028654f * (x + 0.044715f * x3)));
}

__device__ __forceinline__ void packsplit(uint32_t& hi, uint32_t& lo, float a, float b) {
    __nv_bfloat162 h = __floats2bfloat162_rn(a, b);
    float r0 = a - __bfloat162float(__low2bfloat16(h));
    float r1 = b - __bfloat162float(__high2bfloat16(h));
    __nv_bfloat162 l = __floats2bfloat162_rn(r0, r1);
    hi = *reinterpret_cast<uint32_t*>(&h);
    lo = *reinterpret_cast<uint32_t*>(&l);
}

// ---------------- split-transpose: in [Kd][Nd] fp32 -> out[n*ostride + k] bf16 hi/lo ----------------
__global__ void splitT_kernel(const float* __restrict__ in,
                              __nv_bfloat16* __restrict__ hi,
                              __nv_bfloat16* __restrict__ lo,
                              int Kd, int Nd, int ostride) {
    __shared__ float t[32][33];
    int n0 = blockIdx.x * 32, k0 = blockIdx.y * 32;
    int tx = threadIdx.x, ty = threadIdx.y;
#pragma unroll
    for (int j = 0; j < 4; j++)
        t[ty + j * 8][tx] = in[(size_t)(k0 + ty + j * 8) * Nd + n0 + tx];
    __syncthreads();
#pragma unroll
    for (int j = 0; j < 4; j++) {
        float v = t[tx][ty + j * 8];
        int n = n0 + ty + j * 8, k = k0 + tx;
        __nv_bfloat16 h = __float2bfloat16(v);
        hi[(size_t)n * ostride + k] = h;
        lo[(size_t)n * ostride + k] = __float2bfloat16(v - __bfloat162float(h));
    }
}

// ---------------- LayerNorm + split ----------------
__global__ void ln_split_kernel(const float* __restrict__ x,
                                const float* __restrict__ gamma,
                                const float* __restrict__ beta,
                                uint32_t* __restrict__ yh,
                                uint32_t* __restrict__ yl) {
    __shared__ float sh[8];
    __shared__ float stat;
    int row = blockIdx.x;
    int t = threadIdx.x;
    float4 xv = ((const float4*)(x + (size_t)row * D))[t];

    float s = xv.x + xv.y + xv.z + xv.w;
#pragma unroll
    for (int o = 16; o > 0; o >>= 1) s += __shfl_xor_sync(0xffffffffu, s, o);
    if ((t & 31) == 0) sh[t >> 5] = s;
    __syncthreads();
    if (t == 0) {
        float tot = 0.f;
#pragma unroll
        for (int i = 0; i < 8; i++) tot += sh[i];
        stat = tot * (1.f / (float)D);
    }
    __syncthreads();
    float mean = stat;

    float d0 = xv.x - mean, d1 = xv.y - mean, d2 = xv.z - mean, d3 = xv.w - mean;
    float sq = d0 * d0 + d1 * d1 + d2 * d2 + d3 * d3;
#pragma unroll
    for (int o = 16; o > 0; o >>= 1) sq += __shfl_xor_sync(0xffffffffu, sq, o);
    __syncthreads();
    if ((t & 31) == 0) sh[t >> 5] = sq;
    __syncthreads();
    if (t == 0) {
        float tot = 0.f;
#pragma unroll
        for (int i = 0; i < 8; i++) tot += sh[i];
        stat = rsqrtf(tot * (1.f / (float)D) + EPSF);
    }
    __syncthreads();
    float rinv = stat;

    float4 gv = ((const float4*)gamma)[t];
    float4 bv = ((const float4*)beta)[t];
    float v0 = d0 * rinv * gv.x + bv.x;
    float v1 = d1 * rinv * gv.y + bv.y;
    float v2 = d2 * rinv * gv.z + bv.z;
    float v3 = d3 * rinv * gv.w + bv.w;
    uint32_t h0, l0, h1, l1;
    packsplit(h0, l0, v0, v1);
    packsplit(h1, l1, v2, v3);
    int idx = row * (D / 2) + 2 * t;
    yh[idx] = h0; yh[idx + 1] = h1;
    yl[idx] = l0; yl[idx + 1] = l1;
}

// ---------------- fused per-head LN + scale + split for q AND k (one launch) ----------------
__global__ void qknorm_split2(const float* __restrict__ qin, const float* __restrict__ kin,
                              const float* __restrict__ qscale, const float* __restrict__ kscale,
                              uint32_t* __restrict__ qoh, uint32_t* __restrict__ qol,
                              uint32_t* __restrict__ koh, uint32_t* __restrict__ kol) {
    int gid = blockIdx.x * blockDim.x + threadIdx.x;
    int is_k = gid >= S * H;
    int row = is_k ? gid - S * H : gid;
    const float* p = (is_k ? kin : qin) + (size_t)row * DH;
    const float* scale = is_k ? kscale : qscale;
    uint32_t* oh = is_k ? koh : qoh;
    uint32_t* ol = is_k ? kol : qol;
    float sc = is_k ? 1.f : 0.125f;

    float4 v[16];
    float s = 0.f;
#pragma unroll
    for (int i = 0; i < 16; i++) {
        v[i] = ((const float4*)p)[i];
        s += v[i].x + v[i].y + v[i].z + v[i].w;
    }
    float mean = s * (1.f / (float)DH);
    float sq = 0.f;
#pragma unroll
    for (int i = 0; i < 16; i++) {
        v[i].x -= mean; v[i].y -= mean; v[i].z -= mean; v[i].w -= mean;
        sq += v[i].x * v[i].x + v[i].y * v[i].y + v[i].z * v[i].z + v[i].w * v[i].w;
    }
    float r = rsqrtf(sq * (1.f / (float)DH) + EPSF) * sc;
#pragma unroll
    for (int i = 0; i < 16; i++) {
        float4 scv = ((const float4*)scale)[i];
        uint32_t h0, l0, h1, l1;
        packsplit(h0, l0, v[i].x * r * scv.x, v[i].y * r * scv.y);
        packsplit(h1, l1, v[i].z * r * scv.z, v[i].w * r * scv.w);
        int idx = row * (DH / 2) + 2 * i;
        oh[idx] = h0; oh[idx + 1] = h1;
        ol[idx] = l0; ol[idx + 1] = l1;
    }
}

// ================= HMMA GEMM core (round-9 proven mainloop) =================
#define GBM 128
#define GBN 128
#define GBK 32
#define PLANE_B (128 * 40 * 2)        // 10240 B per plane (128 rows x 80 B stride)
#define BUF_B   (4 * PLANE_B)         // Ah, Al, Bh, Bl
#define GSMEM   (2 * BUF_B)           // 81920 B, 2 CTAs/SM

__device__ __forceinline__ void issue_chunk(
    uint32_t base,
    const __nv_bfloat16* Ah, const __nv_bfloat16* Al,
    const __nv_bfloat16* Bh, const __nv_bfloat16* Bl,
    int bm, int bn, int kc, int lda, int ldb, int tid)
{
    int row  = tid >> 1;
    int half = tid & 1;
    uint32_t doff = row * 80 + half * 32;
    size_t aoff = (size_t)(bm + row) * lda + kc + half * 16;
    size_t boff = (size_t)(bn + row) * ldb + kc + half * 16;
    cp16(base + doff,                    Ah + aoff);
    cp16(base + doff + 16,               Ah + aoff + 8);
    cp16(base + PLANE_B + doff,          Al + aoff);
    cp16(base + PLANE_B + doff + 16,     Al + aoff + 8);
    cp16(base + 2 * PLANE_B + doff,      Bh + boff);
    cp16(base + 2 * PLANE_B + doff + 16, Bh + boff + 8);
    cp16(base + 3 * PLANE_B + doff,      Bl + boff);
    cp16(base + 3 * PLANE_B + doff + 16, Bl + boff + 8);
}

__device__ __forceinline__ void hmma_mainloop(
    uint32_t sb, float acc[4][4][4],
    const __nv_bfloat16* Ah, const __nv_bfloat16* Al,
    const __nv_bfloat16* Bh, const __nv_bfloat16* Bl,
    int bm, int bn, int K, int lda, int ldb, int tid, int lane, int wm, int wn)
{
    uint32_t a_off = (uint32_t)((wm * 64 + (lane & 7) + (lane & 8)) * 80 + ((lane >> 4) << 4));
    uint32_t b_off = (uint32_t)((wn * 32 + (lane & 7)) * 80 + ((lane & 8) << 1));

    int nk = K / GBK;
    issue_chunk(sb, Ah, Al, Bh, Bl, bm, bn, 0, lda, ldb, tid);
    CP_COMMIT();

    for (int c = 0; c < nk; c++) {
        CP_WAIT0();
        __syncthreads();
        if (c + 1 < nk) {
            issue_chunk(sb + ((c + 1) & 1) * BUF_B, Ah, Al, Bh, Bl, bm, bn, (c + 1) * GBK, lda, ldb, tid);
            CP_COMMIT();
        }
        uint32_t base = sb + (c & 1) * BUF_B;
        uint32_t aH = base, aL = base + PLANE_B;
        uint32_t bH = base + 2 * PLANE_B, bL = base + 3 * PLANE_B;

#pragma unroll
        for (int k16 = 0; k16 < 2; k16++) {
            uint32_t kb = k16 * 32;
            uint32_t ahf[4][4], bfr[4][2];
#pragma unroll
            for (int mt = 0; mt < 4; mt++) ldmx4(ahf[mt], aH + a_off + mt * 1280 + kb);
#pragma unroll
            for (int nt = 0; nt < 4; nt++) ldmx2(bfr[nt], bH + b_off + nt * 640 + kb);
#pragma unroll
            for (int mt = 0; mt < 4; mt++)
#pragma unroll
                for (int nt = 0; nt < 4; nt++) mma16816(acc[mt][nt], ahf[mt], bfr[nt]);

            uint32_t alf[4][4];
#pragma unroll
            for (int mt = 0; mt < 4; mt++) ldmx4(alf[mt], aL + a_off + mt * 1280 + kb);
#pragma unroll
            for (int mt = 0; mt < 4; mt++)
#pragma unroll
                for (int nt = 0; nt < 4; nt++) mma16816(acc[mt][nt], alf[mt], bfr[nt]);

#pragma unroll
            for (int nt = 0; nt < 4; nt++) ldmx2(bfr[nt], bL + b_off + nt * 640 + kb);
#pragma unroll
            for (int mt = 0; mt < 4; mt++)
#pragma unroll
                for (int nt = 0; nt < 4; nt++) mma16816(acc[mt][nt], ahf[mt], bfr[nt]);
        }
    }
}

// ---- fused GEMM 1: [xn] @ [w_in|wq|wk|wv]^T over N=7168 ----
__global__ void __launch_bounds__(256, 2) hmma_gemm_f1(
    const __nv_bfloat16* __restrict__ Ah, const __nv_bfloat16* __restrict__ Al,
    const __nv_bfloat16* __restrict__ Bh, const __nv_bfloat16* __restrict__ Bl,
    const float* __restrict__ b_in, const float* __restrict__ bq,
    const float* __restrict__ bk, const float* __restrict__ bv,
    uint32_t* __restrict__ acth, uint32_t* __restrict__ actl,
    float* __restrict__ qf, float* __restrict__ kf, float* __restrict__ vf)
{
    extern __shared__ __align__(128) char smem[];
    uint32_t sb = smem_u32(smem);
    int tid = threadIdx.x, lane = tid & 31, wid = tid >> 5;
    int wm = wid >> 2, wn = wid & 3;
    int bm = blockIdx.y * GBM, bn = blockIdx.x * GBN;

    float acc[4][4][4];
#pragma unroll
    for (int i = 0; i < 4; i++)
#pragma unroll
        for (int j = 0; j < 4; j++)
#pragma unroll
            for (int r = 0; r < 4; r++) acc[i][j][r] = 0.f;

    hmma_mainloop(sb, acc, Ah, Al, Bh, Bl, bm, bn, D, D, D, tid, lane, wm, wn);

    int lr = lane >> 2, lc = (lane & 3) * 2;
#pragma unroll
    for (int mt = 0; mt < 4; mt++) {
#pragma unroll
        for (int nt = 0; nt < 4; nt++) {
            float* a = acc[mt][nt];
            int m0 = bm + wm * 64 + mt * 16 + lr;
            int n0 = bn + wn * 32 + nt * 8 + lc;
            if (n0 < F) {
                float b0 = b_in[n0], b1 = b_in[n0 + 1];
                float v0 = gelu_f(a[0] + b0), v1 = gelu_f(a[1] + b1);
                float v2 = gelu_f(a[2] + b0), v3 = gelu_f(a[3] + b1);
                uint32_t h0, l0, h1, l1;
                packsplit(h0, l0, v0, v1);
                packsplit(h1, l1, v2, v3);
                size_t i0 = (size_t)m0 * (K2 / 2) + (n0 >> 1);
                size_t i1 = (size_t)(m0 + 8) * (K2 / 2) + (n0 >> 1);
                acth[i0] = h0; actl[i0] = l0;
                acth[i1] = h1; actl[i1] = l1;
            } else {
                int r = (n0 - F) >> 10;
                int c = (n0 - F) & (D - 1);
                const float* bp = (r == 0) ? bq : (r == 1) ? bk : bv;
                float* dst = (r == 0) ? qf : (r == 1) ? kf : vf;
                float b0 = bp[c], b1 = bp[c + 1];
                float2 w0 = {a[0] + b0, a[1] + b1};
                float2 w1 = {a[2] + b0, a[3] + b1};
                *(float2*)(dst + (size_t)m0 * D + c) = w0;
                *(float2*)(dst + (size_t)(m0 + 8) * D + c) = w1;
            }
        }
    }
}

// ---- accumulate GEMM: C += A @ B^T over K window (strided) ----
__global__ void __launch_bounds__(256, 2) hmma_gemm_acc(
    const __nv_bfloat16* __restrict__ Ah, const __nv_bfloat16* __restrict__ Al,
    const __nv_bfloat16* __restrict__ Bh, const __nv_bfloat16* __restrict__ Bl,
    float* __restrict__ C, int N, int K, int lda, int ldb)
{
    extern __shared__ __align__(128) char smem[];
    uint32_t sb = smem_u32(smem);
    int tid = threadIdx.x, lane = tid & 31, wid = tid >> 5;
    int wm = wid >> 2, wn = wid & 3;
    int bm = blockIdx.y * GBM, bn = blockIdx.x * GBN;

    float acc[4][4][4];
#pragma unroll
    for (int i = 0; i < 4; i++)
#pragma unroll
        for (int j = 0; j < 4; j++)
#pragma unroll
            for (int r = 0; r < 4; r++) acc[i][j][r] = 0.f;

    hmma_mainloop(sb, acc, Ah, Al, Bh, Bl, bm, bn, K, lda, ldb, tid, lane, wm, wn);

    int lr = lane >> 2, lc = (lane & 3) * 2;
#pragma unroll
    for (int mt = 0; mt < 4; mt++) {
#pragma unroll
        for (int nt = 0; nt < 4; nt++) {
            float* a = acc[mt][nt];
            int m0 = bm + wm * 64 + mt * 16 + lr;
            int n0 = bn + wn * 32 + nt * 8 + lc;
            float2* p0 = (float2*)(C + (size_t)m0 * N + n0);
            float2* p1 = (float2*)(C + (size_t)(m0 + 8) * N + n0);
            float2 v0 = *p0, v1 = *p1;
            v0.x += a[0]; v0.y += a[1];
            v1.x += a[2]; v1.y += a[3];
            *p0 = v0; *p1 = v1;
        }
    }
}

// ================= HMMA flash attention (round-9 proven version) =================
#define AT_STRIDE 144
#define AT_PLANE (64 * AT_STRIDE)
#define AT_BUF   (4 * AT_PLANE)
#define AT_QOFF  (2 * AT_BUF)
#define AT_QLO   (128 * AT_STRIDE)
#define AT_SMEM  (2 * AT_BUF + 2 * 128 * AT_STRIDE)

__device__ __forceinline__ void at_load_tile(
    uint32_t dst, const __nv_bfloat16* kh, const __nv_bfloat16* kl,
    const __nv_bfloat16* vth, const __nv_bfloat16* vtl,
    int head, int kt, int tid)
{
    int row = tid >> 2, q4 = tid & 3;
    size_t koff = (size_t)(kt * 64 + row) * D + head * DH + q4 * 16;
    uint32_t d = dst + row * AT_STRIDE + q4 * 32;
    cp16(d,                    kh + koff);
    cp16(d + 16,               kh + koff + 8);
    cp16(d + AT_PLANE,         kl + koff);
    cp16(d + AT_PLANE + 16,    kl + koff + 8);
    size_t voff = (size_t)(head * DH + row) * S + kt * 64 + q4 * 16;
    cp16(d + 2 * AT_PLANE,      vth + voff);
    cp16(d + 2 * AT_PLANE + 16, vth + voff + 8);
    cp16(d + 3 * AT_PLANE,      vtl + voff);
    cp16(d + 3 * AT_PLANE + 16, vtl + voff + 8);
}

__global__ void __launch_bounds__(256, 2) hmma_attn(
    const __nv_bfloat16* __restrict__ qh, const __nv_bfloat16* __restrict__ ql,
    const __nv_bfloat16* __restrict__ kh, const __nv_bfloat16* __restrict__ kl,
    const __nv_bfloat16* __restrict__ vth, const __nv_bfloat16* __restrict__ vtl,
    uint32_t* __restrict__ acth, uint32_t* __restrict__ actl)
{
    extern __shared__ __align__(128) char smem[];
    uint32_t sb = smem_u32(smem);
    int tid = threadIdx.x, lane = tid & 31, wid = tid >> 5;
    int qt = (int)gridDim.x - 1 - (int)blockIdx.x;   // heavy tiles first
    int head = blockIdx.y;
    int ntiles = 2 * qt + 2;

    {
        int row = tid >> 1, half = tid & 1;
        const __nv_bfloat16* s0 = qh + (size_t)(qt * 128 + row) * D + head * DH + half * 32;
        const __nv_bfloat16* s1 = ql + (size_t)(qt * 128 + row) * D + head * DH + half * 32;
        uint32_t dq = sb + AT_QOFF + row * AT_STRIDE + half * 64;
        cp16(dq,      s0); cp16(dq + 16, s0 + 8);
        cp16(dq + 32, s0 + 16); cp16(dq + 48, s0 + 24);
        uint32_t dl = dq + AT_QLO;
        cp16(dl,      s1); cp16(dl + 16, s1 + 8);
        cp16(dl + 32, s1 + 16); cp16(dl + 48, s1 + 24);
    }
    CP_COMMIT();
    at_load_tile(sb, kh, kl, vth, vtl, head, 0, tid);
    CP_COMMIT();
    if (ntiles > 1) { at_load_tile(sb + AT_BUF, kh, kl, vth, vtl, head, 1, tid); CP_COMMIT(); }

    float oacc[8][4];
#pragma unroll
    for (int i = 0; i < 8; i++)
#pragma unroll
        for (int j = 0; j < 4; j++) oacc[i][j] = 0.f;
    float m0 = -INFINITY, m1 = -INFINITY, l0 = 0.f, l1 = 0.f;
    int row0 = qt * 128 + wid * 16 + (lane >> 2);
    uint32_t q_base = sb + AT_QOFF + (wid * 16 + (lane & 15)) * AT_STRIDE + ((lane >> 4) & 1) * 16;

    for (int kt = 0; kt < ntiles; kt++) {
        if (kt + 1 < ntiles) CP_WAIT1(); else CP_WAIT0();
        __syncthreads();
        uint32_t base = sb + (kt & 1) * AT_BUF;

        if (kt * 64 <= qt * 128 + wid * 16 + 15) {
            float s[8][4];
#pragma unroll
            for (int i = 0; i < 8; i++)
#pragma unroll
                for (int j = 0; j < 4; j++) s[i][j] = 0.f;

#pragma unroll
            for (int kc = 0; kc < 4; kc++) {
                uint32_t qh_f[4], ql_f[4];
                ldmx4(qh_f, q_base + kc * 32);
                ldmx4(ql_f, q_base + AT_QLO + kc * 32);
                uint32_t koff = ((lane & 8) << 1) + kc * 32;
#pragma unroll
                for (int nt = 0; nt < 8; nt++) {
                    uint32_t ka = base + (nt * 8 + (lane & 7)) * AT_STRIDE + koff;
                    uint32_t bh[2], bl[2];
                    ldmx2(bh, ka);
                    ldmx2(bl, ka + AT_PLANE);
                    mma16816(s[nt], qh_f, bh);
                    mma16816(s[nt], qh_f, bl);
                    mma16816(s[nt], ql_f, bh);
                }
            }

            if (kt >= 2 * qt) {
#pragma unroll
                for (int nt = 0; nt < 8; nt++) {
                    int c = kt * 64 + nt * 8 + 2 * (lane & 3);
                    if (c     > row0)     s[nt][0] = -INFINITY;
                    if (c + 1 > row0)     s[nt][1] = -INFINITY;
                    if (c     > row0 + 8) s[nt][2] = -INFINITY;
                    if (c + 1 > row0 + 8) s[nt][3] = -INFINITY;
                }
            }

            float mx0 = -INFINITY, mx1 = -INFINITY;
#pragma unroll
            for (int nt = 0; nt < 8; nt++) {
                mx0 = fmaxf(mx0, fmaxf(s[nt][0], s[nt][1]));
                mx1 = fmaxf(mx1, fmaxf(s[nt][2], s[nt][3]));
            }
            mx0 = fmaxf(mx0, __shfl_xor_sync(0xffffffffu, mx0, 1));
            mx0 = fmaxf(mx0, __shfl_xor_sync(0xffffffffu, mx0, 2));
            mx1 = fmaxf(mx1, __shfl_xor_sync(0xffffffffu, mx1, 1));
            mx1 = fmaxf(mx1, __shfl_xor_sync(0xffffffffu, mx1, 2));
            float nm0 = fmaxf(m0, mx0), nm1 = fmaxf(m1, mx1);
            float a0 = __expf(m0 - nm0), a1 = __expf(m1 - nm1);
            m0 = nm0; m1 = nm1;
            float ps0 = 0.f, ps1 = 0.f;
#pragma unroll
            for (int nt = 0; nt < 8; nt++) {
                s[nt][0] = __expf(s[nt][0] - m0); ps0 += s[nt][0];
                s[nt][1] = __expf(s[nt][1] - m0); ps0 += s[nt][1];
                s[nt][2] = __expf(s[nt][2] - m1); ps1 += s[nt][2];
                s[nt][3] = __expf(s[nt][3] - m1); ps1 += s[nt][3];
            }
            l0 = l0 * a0 + ps0;
            l1 = l1 * a1 + ps1;
#pragma unroll
            for (int dt = 0; dt < 8; dt++) {
                oacc[dt][0] *= a0; oacc[dt][1] *= a0;
                oacc[dt][2] *= a1; oacc[dt][3] *= a1;
            }

#pragma unroll
            for (int kc = 0; kc < 4; kc++) {
                uint32_t ph[4], pl[4];
                packsplit(ph[0], pl[0], s[2 * kc][0],     s[2 * kc][1]);
                packsplit(ph[1], pl[1], s[2 * kc][2],     s[2 * kc][3]);
                packsplit(ph[2], pl[2], s[2 * kc + 1][0], s[2 * kc + 1][1]);
                packsplit(ph[3], pl[3], s[2 * kc + 1][2], s[2 * kc + 1][3]);
                uint32_t koff = ((lane & 8) << 1) + kc * 32;
#pragma unroll
                for (int dt = 0; dt < 8; dt++) {
                    uint32_t va = base + 2 * AT_PLANE + (dt * 8 + (lane & 7)) * AT_STRIDE + koff;
                    uint32_t vh[2], vl[2];
                    ldmx2(vh, va);
                    ldmx2(vl, va + AT_PLANE);
                    mma16816(oacc[dt], ph, vh);
                    mma16816(oacc[dt], ph, vl);
                    mma16816(oacc[dt], pl, vh);
                }
            }
        }
        __syncthreads();
        if (kt + 2 < ntiles) { at_load_tile(base, kh, kl, vth, vtl, head, kt + 2, tid); CP_COMMIT(); }
    }

    l0 += __shfl_xor_sync(0xffffffffu, l0, 1);
    l0 += __shfl_xor_sync(0xffffffffu, l0, 2);
    l1 += __shfl_xor_sync(0xffffffffu, l1, 1);
    l1 += __shfl_xor_sync(0xffffffffu, l1, 2);
    float i0 = 1.f / l0, i1 = 1.f / l1;
#pragma unroll
    for (int dt = 0; dt < 8; dt++) {
        int col = F + head * DH + dt * 8 + 2 * (lane & 3);
        uint32_t h0, lo0, h1, lo1;
        packsplit(h0, lo0, oacc[dt][0] * i0, oacc[dt][1] * i0);
        packsplit(h1, lo1, oacc[dt][2] * i1, oacc[dt][3] * i1);
        size_t i0x = (size_t)row0 * (K2 / 2) + (col >> 1);
        size_t i1x = (size_t)(row0 + 8) * (K2 / 2) + (col >> 1);
        acth[i0x] = h0; actl[i0x] = lo0;
        acth[i1x] = h1; actl[i1x] = lo1;
    }
}

// ---------------- out = x + b_mo + b_ao (float4) ----------------
__global__ void init_out_kernel(const float* __restrict__ x,
                                const float* __restrict__ bmo,
                                const float* __restrict__ bao,
                                float* __restrict__ out) {
    int i = blockIdx.x * blockDim.x + threadIdx.x;   // float4 index
    int col4 = i & (D / 4 - 1);
    float4 xv = ((const float4*)x)[i];
    float4 b0 = ((const float4*)bmo)[col4];
    float4 b1 = ((const float4*)bao)[col4];
    float4 o4;
    o4.x = xv.x + b0.x + b1.x;
    o4.y = xv.y + b0.y + b1.y;
    o4.z = xv.z + b0.z + b1.z;
    o4.w = xv.w + b0.w + b1.w;
    ((float4*)out)[i] = o4;
}

// ---------------- launch (round-9 fork-join graph) ----------------
extern "C" void kernel_launch(void* const* d_in, const int* in_sizes, int n_in,
                              void* d_out, int out_size) {
    const float* x        = (const float*)d_in[0];
    // d_in[1] = mask (causal tril) handled analytically
    const float* ln_scale = (const float*)d_in[2];
    const float* ln_bias  = (const float*)d_in[3];
    const float* w_in     = (const float*)d_in[4];
    const float* b_in     = (const float*)d_in[5];
    const float* wq       = (const float*)d_in[6];
    const float* bq       = (const float*)d_in[7];
    const float* wk       = (const float*)d_in[8];
    const float* bk       = (const float*)d_in[9];
    const float* wv       = (const float*)d_in[10];
    const float* bv       = (const float*)d_in[11];
    const float* qn       = (const float*)d_in[12];
    const float* kn       = (const float*)d_in[13];
    const float* w_mo     = (const float*)d_in[14];
    const float* b_mo     = (const float*)d_in[15];
    const float* w_ao     = (const float*)d_in[16];
    const float* b_ao     = (const float*)d_in[17];
    float* out = (float*)d_out;

    float *q, *k, *v;
    cudaGetSymbolAddress((void**)&q, g_q);
    cudaGetSymbolAddress((void**)&k, g_k);
    cudaGetSymbolAddress((void**)&v, g_v);

    __nv_bfloat16 *xnh, *xnl, *acth, *actl, *qsh, *qsl, *ksh, *ksl, *vth, *vtl;
    __nv_bfloat16 *w1h, *w1l, *w2h, *w2l;
    cudaGetSymbolAddress((void**)&xnh, g_xnh);   cudaGetSymbolAddress((void**)&xnl, g_xnl);
    cudaGetSymbolAddress((void**)&acth, g_acth); cudaGetSymbolAddress((void**)&actl, g_actl);
    cudaGetSymbolAddress((void**)&qsh, g_qsh);   cudaGetSymbolAddress((void**)&qsl, g_qsl);
    cudaGetSymbolAddress((void**)&ksh, g_ksh);   cudaGetSymbolAddress((void**)&ksl, g_ksl);
    cudaGetSymbolAddress((void**)&vth, g_vth);   cudaGetSymbolAddress((void**)&vtl, g_vtl);
    cudaGetSymbolAddress((void**)&w1h, g_w1h);   cudaGetSymbolAddress((void**)&w1l, g_w1l);
    cudaGetSymbolAddress((void**)&w2h, g_w2h);   cudaGetSymbolAddress((void**)&w2l, g_w2l);

    cudaFuncSetAttribute(hmma_gemm_f1,  cudaFuncAttributeMaxDynamicSharedMemorySize, GSMEM);
    cudaFuncSetAttribute(hmma_gemm_acc, cudaFuncAttributeMaxDynamicSharedMemorySize, GSMEM);
    cudaFuncSetAttribute(hmma_attn,     cudaFuncAttributeMaxDynamicSharedMemorySize, AT_SMEM);

    static cudaStream_t side = nullptr;
    static cudaEvent_t ev_fork = nullptr, ev_f1 = nullptr, ev_side = nullptr;
    if (!side) {
        cudaStreamCreateWithFlags(&side, cudaStreamNonBlocking);
        cudaEventCreateWithFlags(&ev_fork, cudaEventDisableTiming);
        cudaEventCreateWithFlags(&ev_f1,   cudaEventDisableTiming);
        cudaEventCreateWithFlags(&ev_side, cudaEventDisableTiming);
    }

    cudaEventRecord(ev_fork, 0);
    cudaStreamWaitEvent(side, ev_fork, 0);

    // side: w2 packing + out init
    splitT_kernel<<<dim3(D / 32, F / 32), dim3(32, 8), 0, side>>>(w_mo, w2h, w2l, F, D, K2);
    splitT_kernel<<<dim3(D / 32, D / 32), dim3(32, 8), 0, side>>>(w_ao, w2h + F, w2l + F, D, D, K2);
    init_out_kernel<<<(S * D / 4) / 256, 256, 0, side>>>(x, b_mo, b_ao, out);

    // main: w1 packing, LN, fused f1 GEMM
    splitT_kernel<<<dim3(F / 32, D / 32), dim3(32, 8)>>>(w_in, w1h, w1l, D, F, D);
    splitT_kernel<<<dim3(D / 32, D / 32), dim3(32, 8)>>>(wq, w1h + (size_t)F * D, w1l + (size_t)F * D, D, D, D);
    splitT_kernel<<<dim3(D / 32, D / 32), dim3(32, 8)>>>(wk, w1h + (size_t)(F + D) * D, w1l + (size_t)(F + D) * D, D, D, D);
    splitT_kernel<<<dim3(D / 32, D / 32), dim3(32, 8)>>>(wv, w1h + (size_t)(F + 2 * D) * D, w1l + (size_t)(F + 2 * D) * D, D, D, D);
    ln_split_kernel<<<S, 256>>>(x, ln_scale, ln_bias, (uint32_t*)xnh, (uint32_t*)xnl);
    hmma_gemm_f1<<<dim3(N1 / GBN, S / GBM), 256, GSMEM>>>(
        xnh, xnl, w1h, w1l, b_in, bq, bk, bv,
        (uint32_t*)acth, (uint32_t*)actl, q, k, v);
    cudaEventRecord(ev_f1, 0);

    // side: out += h @ w_mo — overlaps attention path
    cudaStreamWaitEvent(side, ev_f1, 0);
    hmma_gemm_acc<<<dim3(D / GBN, S / GBM), 256, GSMEM, side>>>(
        acth, actl, w2h, w2l, out, D, F, K2, K2);
    cudaEventRecord(ev_side, side);

    // main: fused qk-norm (q and k in one launch), V split-transpose, attention
    qknorm_split2<<<(2 * S * H) / 256, 256>>>(q, k, qn, kn,
                                              (uint32_t*)qsh, (uint32_t*)qsl,
                                              (uint32_t*)ksh, (uint32_t*)ksl);
    splitT_kernel<<<dim3(D / 32, S / 32), dim3(32, 8)>>>(v, vth, vtl, S, D, S);
    hmma_attn<<<dim3(S / 128, H), 256, AT_SMEM>>>(qsh, qsl, ksh, ksl, vth, vtl,
                                                  (uint32_t*)acth, (uint32_t*)actl);

    // join, then out += o @ w_ao (K window [4096, 5120))
    cudaStreamWaitEvent(0, ev_side, 0);
    hmma_gemm_acc<<<dim3(D / GBN, S / GBM), 256, GSMEM>>>(
        acth + F, actl + F, w2h + F, w2l + F, out, D, D, K2, K2);
}

// round 15
// speedup vs baseline: 1.7902x; 1.0970x over previous
#include <cuda_runtime.h>
#include <cuda_bf16.h>
#include <math.h>
#include <stdint.h>

#define S 4096
#define D 1024
#define H 16
#define DH 64
#define F 4096
#define N3 3072              // 3*D : QKV output width
#define EPSF 1e-6f

// ---------------- scratch (device globals: alloc-free) ----------------
__device__ float g_q [S * D];
__device__ float g_k [S * D];
__device__ float g_v [S * D];

__device__ __nv_bfloat16 g_xnh[S * D], g_xnl[S * D];       // LN output bf16 planes (qkv GEMM)
__device__ uint32_t      g_xnt[S * D];                     // LN output tf32 (h GEMM)
__device__ __nv_bfloat16 g_wqkvh[N3 * D], g_wqkvl[N3 * D]; // [wq|wk|wv]^T bf16 planes
__device__ uint32_t      g_wint[F * D];                    // w_in^T tf32 [F][D]
__device__ uint32_t      g_ht [S * F];                     // h tf32 [S][F]
__device__ uint32_t      g_wmot[D * F];                    // w_mo^T tf32 [D][F]
__device__ __nv_bfloat16 g_oh [S * D], g_ol [S * D];       // attention o bf16 planes
__device__ __nv_bfloat16 g_waoh[D * D], g_waol[D * D];     // w_ao^T bf16 planes
__device__ __nv_bfloat16 g_qsh[S * D], g_qsl[S * D];       // q * 1/8 planes
__device__ __nv_bfloat16 g_ksh[S * D], g_ksl[S * D];       // k planes
__device__ __nv_bfloat16 g_vth[D * S], g_vtl[D * S];       // V^T planes

// ---------------- asm helpers (base sm_103 instructions) ----------------
__device__ __forceinline__ uint32_t smem_u32(const void* p) {
    uint32_t a;
    asm("{ .reg .u64 t; cvta.to.shared.u64 t, %1; cvt.u32.u64 %0, t; }" : "=r"(a) : "l"(p));
    return a;
}
__device__ __forceinline__ void cp16(uint32_t d, const void* s) {
    asm volatile("cp.async.cg.shared.global [%0], [%1], 16;" :: "r"(d), "l"(s));
}
#define CP_COMMIT() asm volatile("cp.async.commit_group;" ::: "memory")
#define CP_WAIT1()  asm volatile("cp.async.wait_group 1;" ::: "memory")
#define CP_WAIT0()  asm volatile("cp.async.wait_group 0;" ::: "memory")

__device__ __forceinline__ void ldmx4(uint32_t* r, uint32_t a) {
    asm volatile("ldmatrix.sync.aligned.m8n8.x4.shared.b16 {%0,%1,%2,%3}, [%4];"
                 : "=r"(r[0]), "=r"(r[1]), "=r"(r[2]), "=r"(r[3]) : "r"(a));
}
__device__ __forceinline__ void ldmx2(uint32_t* r, uint32_t a) {
    asm volatile("ldmatrix.sync.aligned.m8n8.x2.shared.b16 {%0,%1}, [%2];"
                 : "=r"(r[0]), "=r"(r[1]) : "r"(a));
}
__device__ __forceinline__ void mma16816(float* c, const uint32_t* a, const uint32_t* b) {
    asm volatile("mma.sync.aligned.m16n8k16.row.col.f32.bf16.bf16.f32 "
                 "{%0,%1,%2,%3}, {%4,%5,%6,%7}, {%8,%9}, {%0,%1,%2,%3};"
                 : "+f"(c[0]), "+f"(c[1]), "+f"(c[2]), "+f"(c[3])
                 : "r"(a[0]), "r"(a[1]), "r"(a[2]), "r"(a[3]), "r"(b[0]), "r"(b[1]));
}
__device__ __forceinline__ void mma_t32(float* c, const uint32_t* a, const uint32_t* b) {
    asm volatile("mma.sync.aligned.m16n8k8.row.col.f32.tf32.tf32.f32 "
                 "{%0,%1,%2,%3}, {%4,%5,%6,%7}, {%8,%9}, {%0,%1,%2,%3};"
                 : "+f"(c[0]), "+f"(c[1]), "+f"(c[2]), "+f"(c[3])
                 : "r"(a[0]), "r"(a[1]), "r"(a[2]), "r"(a[3]), "r"(b[0]), "r"(b[1]));
}
__device__ __forceinline__ uint32_t to_tf32(float x) {
    uint32_t u;
    asm("cvt.rna.tf32.f32 %0, %1;" : "=r"(u) : "f"(x));
    return u;
}

__device__ __forceinline__ float gelu_f(float x) {
    float x3 = x * x * x;
    return 0.5f * x * (1.f + tanhf(0.7978845608028654f * (x + 0.044715f * x3)));
}

__device__ __forceinline__ void packsplit(uint32_t& hi, uint32_t& lo, float a, float b) {
    __nv_bfloat162 h = __floats2bfloat162_rn(a, b);
    float r0 = a - __bfloat162float(__low2bfloat16(h));
    float r1 = b - __bfloat162float(__high2bfloat16(h));
    __nv_bfloat162 l = __floats2bfloat162_rn(r0, r1);
    hi = *reinterpret_cast<uint32_t*>(&h);
    lo = *reinterpret_cast<uint32_t*>(&l);
}

// ---------------- split-transpose (bf16 hi/lo): [Kd][Nd] fp32 -> [n][k] ----------------
__global__ void splitT_kernel(const float* __restrict__ in,
                              __nv_bfloat16* __restrict__ hi,
                              __nv_bfloat16* __restrict__ lo,
                              int Kd, int Nd, int ostride) {
    __shared__ float t[32][33];
    int n0 = blockIdx.x * 32, k0 = blockIdx.y * 32;
    int tx = threadIdx.x, ty = threadIdx.y;
#pragma unroll
    for (int j = 0; j < 4; j++)
        t[ty + j * 8][tx] = in[(size_t)(k0 + ty + j * 8) * Nd + n0 + tx];
    __syncthreads();
#pragma unroll
    for (int j = 0; j < 4; j++) {
        float v = t[tx][ty + j * 8];
        int n = n0 + ty + j * 8, k = k0 + tx;
        __nv_bfloat16 h = __float2bfloat16(v);
        hi[(size_t)n * ostride + k] = h;
        lo[(size_t)n * ostride + k] = __float2bfloat16(v - __bfloat162float(h));
    }
}

// ---------------- transpose to tf32: [Kd][Nd] fp32 -> [n][k] tf32 ----------------
__global__ void splitT_tf32(const float* __restrict__ in,
                            uint32_t* __restrict__ out,
                            int Kd, int Nd, int ostride) {
    __shared__ float t[32][33];
    int n0 = blockIdx.x * 32, k0 = blockIdx.y * 32;
    int tx = threadIdx.x, ty = threadIdx.y;
#pragma unroll
    for (int j = 0; j < 4; j++)
        t[ty + j * 8][tx] = in[(size_t)(k0 + ty + j * 8) * Nd + n0 + tx];
    __syncthreads();
#pragma unroll
    for (int j = 0; j < 4; j++) {
        int n = n0 + ty + j * 8, k = k0 + tx;
        out[(size_t)n * ostride + k] = to_tf32(t[tx][ty + j * 8]);
    }
}

// ---------------- LayerNorm + split (bf16 planes + tf32 plane) ----------------
__global__ void ln_split_kernel(const float* __restrict__ x,
                                const float* __restrict__ gamma,
                                const float* __restrict__ beta,
                                uint32_t* __restrict__ yh,
                                uint32_t* __restrict__ yl,
                                uint32_t* __restrict__ yt) {
    __shared__ float sh[8];
    __shared__ float stat;
    int row = blockIdx.x;
    int t = threadIdx.x;
    float4 xv = ((const float4*)(x + (size_t)row * D))[t];

    float s = xv.x + xv.y + xv.z + xv.w;
#pragma unroll
    for (int o = 16; o > 0; o >>= 1) s += __shfl_xor_sync(0xffffffffu, s, o);
    if ((t & 31) == 0) sh[t >> 5] = s;
    __syncthreads();
    if (t == 0) {
        float tot = 0.f;
#pragma unroll
        for (int i = 0; i < 8; i++) tot += sh[i];
        stat = tot * (1.f / (float)D);
    }
    __syncthreads();
    float mean = stat;

    float d0 = xv.x - mean, d1 = xv.y - mean, d2 = xv.z - mean, d3 = xv.w - mean;
    float sq = d0 * d0 + d1 * d1 + d2 * d2 + d3 * d3;
#pragma unroll
    for (int o = 16; o > 0; o >>= 1) sq += __shfl_xor_sync(0xffffffffu, sq, o);
    __syncthreads();
    if ((t & 31) == 0) sh[t >> 5] = sq;
    __syncthreads();
    if (t == 0) {
        float tot = 0.f;
#pragma unroll
        for (int i = 0; i < 8; i++) tot += sh[i];
        stat = rsqrtf(tot * (1.f / (float)D) + EPSF);
    }
    __syncthreads();
    float rinv = stat;

    float4 gv = ((const float4*)gamma)[t];
    float4 bv = ((const float4*)beta)[t];
    float v0 = d0 * rinv * gv.x + bv.x;
    float v1 = d1 * rinv * gv.y + bv.y;
    float v2 = d2 * rinv * gv.z + bv.z;
    float v3 = d3 * rinv * gv.w + bv.w;
    uint32_t h0, l0, h1, l1;
    packsplit(h0, l0, v0, v1);
    packsplit(h1, l1, v2, v3);
    int idx = row * (D / 2) + 2 * t;
    yh[idx] = h0; yh[idx + 1] = h1;
    yl[idx] = l0; yl[idx + 1] = l1;
    uint4 tv = {to_tf32(v0), to_tf32(v1), to_tf32(v2), to_tf32(v3)};
    ((uint4*)yt)[row * (D / 4) + t] = tv;
}

// ---------------- fused per-head LN + scale + split for q AND k ----------------
__global__ void qknorm_split2(const float* __restrict__ qin, const float* __restrict__ kin,
                              const float* __restrict__ qscale, const float* __restrict__ kscale,
                              uint32_t* __restrict__ qoh, uint32_t* __restrict__ qol,
                              uint32_t* __restrict__ koh, uint32_t* __restrict__ kol) {
    int gid = blockIdx.x * blockDim.x + threadIdx.x;
    int is_k = gid >= S * H;
    int row = is_k ? gid - S * H : gid;
    const float* p = (is_k ? kin : qin) + (size_t)row * DH;
    const float* scale = is_k ? kscale : qscale;
    uint32_t* oh = is_k ? koh : qoh;
    uint32_t* ol = is_k ? kol : qol;
    float sc = is_k ? 1.f : 0.125f;

    float4 v[16];
    float s = 0.f;
#pragma unroll
    for (int i = 0; i < 16; i++) {
        v[i] = ((const float4*)p)[i];
        s += v[i].x + v[i].y + v[i].z + v[i].w;
    }
    float mean = s * (1.f / (float)DH);
    float sq = 0.f;
#pragma unroll
    for (int i = 0; i < 16; i++) {
        v[i].x -= mean; v[i].y -= mean; v[i].z -= mean; v[i].w -= mean;
        sq += v[i].x * v[i].x + v[i].y * v[i].y + v[i].z * v[i].z + v[i].w * v[i].w;
    }
    float r = rsqrtf(sq * (1.f / (float)DH) + EPSF) * sc;
#pragma unroll
    for (int i = 0; i < 16; i++) {
        float4 scv = ((const float4*)scale)[i];
        uint32_t h0, l0, h1, l1;
        packsplit(h0, l0, v[i].x * r * scv.x, v[i].y * r * scv.y);
        packsplit(h1, l1, v[i].z * r * scv.z, v[i].w * r * scv.w);
        int idx = row * (DH / 2) + 2 * i;
        oh[idx] = h0; oh[idx + 1] = h1;
        ol[idx] = l0; ol[idx + 1] = l1;
    }
}

// ================= bf16 3-term HMMA GEMM core (round-9 proven) =================
#define GBM 128
#define GBN 128
#define GBK 32
#define PLANE_B (128 * 40 * 2)
#define BUF_B   (4 * PLANE_B)
#define GSMEM   (2 * BUF_B)

__device__ __forceinline__ void issue_chunk(
    uint32_t base,
    const __nv_bfloat16* Ah, const __nv_bfloat16* Al,
    const __nv_bfloat16* Bh, const __nv_bfloat16* Bl,
    int bm, int bn, int kc, int lda, int ldb, int tid)
{
    int row  = tid >> 1;
    int half = tid & 1;
    uint32_t doff = row * 80 + half * 32;
    size_t aoff = (size_t)(bm + row) * lda + kc + half * 16;
    size_t boff = (size_t)(bn + row) * ldb + kc + half * 16;
    cp16(base + doff,                    Ah + aoff);
    cp16(base + doff + 16,               Ah + aoff + 8);
    cp16(base + PLANE_B + doff,          Al + aoff);
    cp16(base + PLANE_B + doff + 16,     Al + aoff + 8);
    cp16(base + 2 * PLANE_B + doff,      Bh + boff);
    cp16(base + 2 * PLANE_B + doff + 16, Bh + boff + 8);
    cp16(base + 3 * PLANE_B + doff,      Bl + boff);
    cp16(base + 3 * PLANE_B + doff + 16, Bl + boff + 8);
}

__device__ __forceinline__ void hmma_mainloop(
    uint32_t sb, float acc[4][4][4],
    const __nv_bfloat16* Ah, const __nv_bfloat16* Al,
    const __nv_bfloat16* Bh, const __nv_bfloat16* Bl,
    int bm, int bn, int K, int lda, int ldb, int tid, int lane, int wm, int wn)
{
    uint32_t a_off = (uint32_t)((wm * 64 + (lane & 7) + (lane & 8)) * 80 + ((lane >> 4) << 4));
    uint32_t b_off = (uint32_t)((wn * 32 + (lane & 7)) * 80 + ((lane & 8) << 1));

    int nk = K / GBK;
    issue_chunk(sb, Ah, Al, Bh, Bl, bm, bn, 0, lda, ldb, tid);
    CP_COMMIT();

    for (int c = 0; c < nk; c++) {
        CP_WAIT0();
        __syncthreads();
        if (c + 1 < nk) {
            issue_chunk(sb + ((c + 1) & 1) * BUF_B, Ah, Al, Bh, Bl, bm, bn, (c + 1) * GBK, lda, ldb, tid);
            CP_COMMIT();
        }
        uint32_t base = sb + (c & 1) * BUF_B;
        uint32_t aH = base, aL = base + PLANE_B;
        uint32_t bH = base + 2 * PLANE_B, bL = base + 3 * PLANE_B;

#pragma unroll
        for (int k16 = 0; k16 < 2; k16++) {
            uint32_t kb = k16 * 32;
            uint32_t ahf[4][4], bfr[4][2];
#pragma unroll
            for (int mt = 0; mt < 4; mt++) ldmx4(ahf[mt], aH + a_off + mt * 1280 + kb);
#pragma unroll
            for (int nt = 0; nt < 4; nt++) ldmx2(bfr[nt], bH + b_off + nt * 640 + kb);
#pragma unroll
            for (int mt = 0; mt < 4; mt++)
#pragma unroll
                for (int nt = 0; nt < 4; nt++) mma16816(acc[mt][nt], ahf[mt], bfr[nt]);

            uint32_t alf[4][4];
#pragma unroll
            for (int mt = 0; mt < 4; mt++) ldmx4(alf[mt], aL + a_off + mt * 1280 + kb);
#pragma unroll
            for (int mt = 0; mt < 4; mt++)
#pragma unroll
                for (int nt = 0; nt < 4; nt++) mma16816(acc[mt][nt], alf[mt], bfr[nt]);

#pragma unroll
            for (int nt = 0; nt < 4; nt++) ldmx2(bfr[nt], bL + b_off + nt * 640 + kb);
#pragma unroll
            for (int mt = 0; mt < 4; mt++)
#pragma unroll
                for (int nt = 0; nt < 4; nt++) mma16816(acc[mt][nt], ahf[mt], bfr[nt]);
        }
    }
}

// ================= tf32 1-term GEMM core =================
// stride 144 B/row (32 tf32 + 16B pad; 144 mod 128 = 16 -> conflict-free ldmatrix phases)
#define TF_STRIDE 144
#define TF_PLANE (128 * TF_STRIDE)      // 18432 B
#define TF_BUF   (2 * TF_PLANE)         // A + B
#define TF_SMEM  (2 * TF_BUF)           // 73728 B, 2 CTAs/SM

__device__ __forceinline__ void issue_chunk_t(
    uint32_t base, const uint32_t* A, const uint32_t* B,
    int bm, int bn, int kc, int lda, int ldb, int tid)
{
    int row = tid >> 1, half = tid & 1;
    uint32_t doff = row * TF_STRIDE + half * 64;
    size_t aoff = (size_t)(bm + row) * lda + kc + half * 16;
    size_t boff = (size_t)(bn + row) * ldb + kc + half * 16;
    cp16(base + doff,      A + aoff);
    cp16(base + doff + 16, A + aoff + 4);
    cp16(base + doff + 32, A + aoff + 8);
    cp16(base + doff + 48, A + aoff + 12);
    uint32_t d2 = base + TF_PLANE + doff;
    cp16(d2,      B + boff);
    cp16(d2 + 16, B + boff + 4);
    cp16(d2 + 32, B + boff + 8);
    cp16(d2 + 48, B + boff + 12);
}

__device__ __forceinline__ void tf32_mainloop(
    uint32_t sb, float acc[4][4][4],
    const uint32_t* A, const uint32_t* B,
    int bm, int bn, int K, int lda, int ldb, int tid, int lane, int wm, int wn)
{
    uint32_t a_off = (uint32_t)((wm * 64 + (lane & 7) + (lane & 8)) * TF_STRIDE + ((lane >> 4) << 4));
    uint32_t b_off = (uint32_t)((wn * 32 + (lane & 7)) * TF_STRIDE + ((lane & 8) << 1));

    int nk = K / GBK;
    issue_chunk_t(sb, A, B, bm, bn, 0, lda, ldb, tid);
    CP_COMMIT();

    for (int c = 0; c < nk; c++) {
        CP_WAIT0();
        __syncthreads();
        if (c + 1 < nk) {
            issue_chunk_t(sb + ((c + 1) & 1) * TF_BUF, A, B, bm, bn, (c + 1) * GBK, lda, ldb, tid);
            CP_COMMIT();
        }
        uint32_t base = sb + (c & 1) * TF_BUF;
        uint32_t aP = base, bP = base + TF_PLANE;

#pragma unroll
        for (int k8 = 0; k8 < 4; k8++) {
            uint32_t kb = k8 * 32;
            uint32_t af[4][4], bf[4][2];
#pragma unroll
            for (int mt = 0; mt < 4; mt++) ldmx4(af[mt], aP + a_off + mt * 16 * TF_STRIDE + kb);
#pragma unroll
            for (int nt = 0; nt < 4; nt++) ldmx2(bf[nt], bP + b_off + nt * 8 * TF_STRIDE + kb);
#pragma unroll
            for (int mt = 0; mt < 4; mt++)
#pragma unroll
                for (int nt = 0; nt < 4; nt++) mma_t32(acc[mt][nt], af[mt], bf[nt]);
        }
    }
}

// ---- f1qkv (bf16): [q|k|v] = xn @ [wq|wk|wv]^T + bias ----
__global__ void __launch_bounds__(256, 2) hmma_gemm_qkv(
    const __nv_bfloat16* __restrict__ Ah, const __nv_bfloat16* __restrict__ Al,
    const __nv_bfloat16* __restrict__ Bh, const __nv_bfloat16* __restrict__ Bl,
    const float* __restrict__ bq, const float* __restrict__ bk, const float* __restrict__ bv,
    float* __restrict__ qf, float* __restrict__ kf, float* __restrict__ vf)
{
    extern __shared__ __align__(128) char smem[];
    uint32_t sb = smem_u32(smem);
    int tid = threadIdx.x, lane = tid & 31, wid = tid >> 5;
    int wm = wid >> 2, wn = wid & 3;
    int bm = blockIdx.y * GBM, bn = blockIdx.x * GBN;

    float acc[4][4][4];
#pragma unroll
    for (int i = 0; i < 4; i++)
#pragma unroll
        for (int j = 0; j < 4; j++)
#pragma unroll
            for (int r = 0; r < 4; r++) acc[i][j][r] = 0.f;

    hmma_mainloop(sb, acc, Ah, Al, Bh, Bl, bm, bn, D, D, D, tid, lane, wm, wn);

    int lr = lane >> 2, lc = (lane & 3) * 2;
#pragma unroll
    for (int mt = 0; mt < 4; mt++) {
#pragma unroll
        for (int nt = 0; nt < 4; nt++) {
            float* a = acc[mt][nt];
            int m0 = bm + wm * 64 + mt * 16 + lr;
            int n0 = bn + wn * 32 + nt * 8 + lc;
            int r = n0 >> 10;
            int c = n0 & (D - 1);
            const float* bp = (r == 0) ? bq : (r == 1) ? bk : bv;
            float* dst = (r == 0) ? qf : (r == 1) ? kf : vf;
            float b0 = bp[c], b1 = bp[c + 1];
            float2 w0 = {a[0] + b0, a[1] + b1};
            float2 w1 = {a[2] + b0, a[3] + b1};
            *(float2*)(dst + (size_t)m0 * D + c) = w0;
            *(float2*)(dst + (size_t)(m0 + 8) * D + c) = w1;
        }
    }
}

// ---- f1h (tf32): h = gelu(xn_t @ w_in^T + b_in), stored tf32 ----
__global__ void __launch_bounds__(256, 2) tf32_gemm_h(
    const uint32_t* __restrict__ A, const uint32_t* __restrict__ B,
    const float* __restrict__ b_in, uint32_t* __restrict__ ht)
{
    extern __shared__ __align__(128) char smem[];
    uint32_t sb = smem_u32(smem);
    int tid = threadIdx.x, lane = tid & 31, wid = tid >> 5;
    int wm = wid >> 2, wn = wid & 3;
    int bm = blockIdx.y * GBM, bn = blockIdx.x * GBN;

    float acc[4][4][4];
#pragma unroll
    for (int i = 0; i < 4; i++)
#pragma unroll
        for (int j = 0; j < 4; j++)
#pragma unroll
            for (int r = 0; r < 4; r++) acc[i][j][r] = 0.f;

    tf32_mainloop(sb, acc, A, B, bm, bn, D, D, D, tid, lane, wm, wn);

    int lr = lane >> 2, lc = (lane & 3) * 2;
#pragma unroll
    for (int mt = 0; mt < 4; mt++) {
#pragma unroll
        for (int nt = 0; nt < 4; nt++) {
            float* a = acc[mt][nt];
            int m0 = bm + wm * 64 + mt * 16 + lr;
            int n0 = bn + wn * 32 + nt * 8 + lc;
            float b0 = b_in[n0], b1 = b_in[n0 + 1];
            uint2 w0 = {to_tf32(gelu_f(a[0] + b0)), to_tf32(gelu_f(a[1] + b1))};
            uint2 w1 = {to_tf32(gelu_f(a[2] + b0)), to_tf32(gelu_f(a[3] + b1))};
            *(uint2*)(ht + (size_t)m0 * F + n0) = w0;
            *(uint2*)(ht + (size_t)(m0 + 8) * F + n0) = w1;
        }
    }
}

// ---- w_mo (tf32): out += h_t @ w_mo^T ----
__global__ void __launch_bounds__(256, 2) tf32_gemm_acc(
    const uint32_t* __restrict__ A, const uint32_t* __restrict__ B,
    float* __restrict__ C)
{
    extern __shared__ __align__(128) char smem[];
    uint32_t sb = smem_u32(smem);
    int tid = threadIdx.x, lane = tid & 31, wid = tid >> 5;
    int wm = wid >> 2, wn = wid & 3;
    int bm = blockIdx.y * GBM, bn = blockIdx.x * GBN;

    float acc[4][4][4];
#pragma unroll
    for (int i = 0; i < 4; i++)
#pragma unroll
        for (int j = 0; j < 4; j++)
#pragma unroll
            for (int r = 0; r < 4; r++) acc[i][j][r] = 0.f;

    tf32_mainloop(sb, acc, A, B, bm, bn, F, F, F, tid, lane, wm, wn);

    int lr = lane >> 2, lc = (lane & 3) * 2;
#pragma unroll
    for (int mt = 0; mt < 4; mt++) {
#pragma unroll
        for (int nt = 0; nt < 4; nt++) {
            float* a = acc[mt][nt];
            int m0 = bm + wm * 64 + mt * 16 + lr;
            int n0 = bn + wn * 32 + nt * 8 + lc;
            float2* p0 = (float2*)(C + (size_t)m0 * D + n0);
            float2* p1 = (float2*)(C + (size_t)(m0 + 8) * D + n0);
            float2 v0 = *p0, v1 = *p1;
            v0.x += a[0]; v0.y += a[1];
            v1.x += a[2]; v1.y += a[3];
            *p0 = v0; *p1 = v1;
        }
    }
}

// ---- o @ w_ao (bf16 3-term): out += o @ w_ao^T ----
__global__ void __launch_bounds__(256, 2) hmma_gemm_acc(
    const __nv_bfloat16* __restrict__ Ah, const __nv_bfloat16* __restrict__ Al,
    const __nv_bfloat16* __restrict__ Bh, const __nv_bfloat16* __restrict__ Bl,
    float* __restrict__ C, int N, int K, int lda, int ldb)
{
    extern __shared__ __align__(128) char smem[];
    uint32_t sb = smem_u32(smem);
    int tid = threadIdx.x, lane = tid & 31, wid = tid >> 5;
    int wm = wid >> 2, wn = wid & 3;
    int bm = blockIdx.y * GBM, bn = blockIdx.x * GBN;

    float acc[4][4][4];
#pragma unroll
    for (int i = 0; i < 4; i++)
#pragma unroll
        for (int j = 0; j < 4; j++)
#pragma unroll
            for (int r = 0; r < 4; r++) acc[i][j][r] = 0.f;

    hmma_mainloop(sb, acc, Ah, Al, Bh, Bl, bm, bn, K, lda, ldb, tid, lane, wm, wn);

    int lr = lane >> 2, lc = (lane & 3) * 2;
#pragma unroll
    for (int mt = 0; mt < 4; mt++) {
#pragma unroll
        for (int nt = 0; nt < 4; nt++) {
            float* a = acc[mt][nt];
            int m0 = bm + wm * 64 + mt * 16 + lr;
            int n0 = bn + wn * 32 + nt * 8 + lc;
            float2* p0 = (float2*)(C + (size_t)m0 * N + n0);
            float2* p1 = (float2*)(C + (size_t)(m0 + 8) * N + n0);
            float2 v0 = *p0, v1 = *p1;
            v0.x += a[0]; v0.y += a[1];
            v1.x += a[2]; v1.y += a[3];
            *p0 = v0; *p1 = v1;
        }
    }
}

// ================= HMMA flash attention (round-9 proven; o planes stride D) =================
#define AT_STRIDE 144
#define AT_PLANE (64 * AT_STRIDE)
#define AT_BUF   (4 * AT_PLANE)
#define AT_QOFF  (2 * AT_BUF)
#define AT_QLO   (128 * AT_STRIDE)
#define AT_SMEM  (2 * AT_BUF + 2 * 128 * AT_STRIDE)

__device__ __forceinline__ void at_load_tile(
    uint32_t dst, const __nv_bfloat16* kh, const __nv_bfloat16* kl,
    const __nv_bfloat16* vth, const __nv_bfloat16* vtl,
    int head, int kt, int tid)
{
    int row = tid >> 2, q4 = tid & 3;
    size_t koff = (size_t)(kt * 64 + row) * D + head * DH + q4 * 16;
    uint32_t d = dst + row * AT_STRIDE + q4 * 32;
    cp16(d,                    kh + koff);
    cp16(d + 16,               kh + koff + 8);
    cp16(d + AT_PLANE,         kl + koff);
    cp16(d + AT_PLANE + 16,    kl + koff + 8);
    size_t voff = (size_t)(head * DH + row) * S + kt * 64 + q4 * 16;
    cp16(d + 2 * AT_PLANE,      vth + voff);
    cp16(d + 2 * AT_PLANE + 16, vth + voff + 8);
    cp16(d + 3 * AT_PLANE,      vtl + voff);
    cp16(d + 3 * AT_PLANE + 16, vtl + voff + 8);
}

__global__ void __launch_bounds__(256, 2) hmma_attn(
    const __nv_bfloat16* __restrict__ qh, const __nv_bfloat16* __restrict__ ql,
    const __nv_bfloat16* __restrict__ kh, const __nv_bfloat16* __restrict__ kl,
    const __nv_bfloat16* __restrict__ vth, const __nv_bfloat16* __restrict__ vtl,
    uint32_t* __restrict__ ohp, uint32_t* __restrict__ olp)
{
    extern __shared__ __align__(128) char smem[];
    uint32_t sb = smem_u32(smem);
    int tid = threadIdx.x, lane = tid & 31, wid = tid >> 5;
    int qt = (int)gridDim.x - 1 - (int)blockIdx.x;   // heavy tiles first
    int head = blockIdx.y;
    int ntiles = 2 * qt + 2;

    {
        int row = tid >> 1, half = tid & 1;
        const __nv_bfloat16* s0 = qh + (size_t)(qt * 128 + row) * D + head * DH + half * 32;
        const __nv_bfloat16* s1 = ql + (size_t)(qt * 128 + row) * D + head * DH + half * 32;
        uint32_t dq = sb + AT_QOFF + row * AT_STRIDE + half * 64;
        cp16(dq,      s0); cp16(dq + 16, s0 + 8);
        cp16(dq + 32, s0 + 16); cp16(dq + 48, s0 + 24);
        uint32_t dl = dq + AT_QLO;
        cp16(dl,      s1); cp16(dl + 16, s1 + 8);
        cp16(dl + 32, s1 + 16); cp16(dl + 48, s1 + 24);
    }
    CP_COMMIT();
    at_load_tile(sb, kh, kl, vth, vtl, head, 0, tid);
    CP_COMMIT();
    if (ntiles > 1) { at_load_tile(sb + AT_BUF, kh, kl, vth, vtl, head, 1, tid); CP_COMMIT(); }

    float oacc[8][4];
#pragma unroll
    for (int i = 0; i < 8; i++)
#pragma unroll
        for (int j = 0; j < 4; j++) oacc[i][j] = 0.f;
    float m0 = -INFINITY, m1 = -INFINITY, l0 = 0.f, l1 = 0.f;
    int row0 = qt * 128 + wid * 16 + (lane >> 2);
    uint32_t q_base = sb + AT_QOFF + (wid * 16 + (lane & 15)) * AT_STRIDE + ((lane >> 4) & 1) * 16;

    for (int kt = 0; kt < ntiles; kt++) {
        if (kt + 1 < ntiles) CP_WAIT1(); else CP_WAIT0();
        __syncthreads();
        uint32_t base = sb + (kt & 1) * AT_BUF;

        if (kt * 64 <= qt * 128 + wid * 16 + 15) {
            float s[8][4];
#pragma unroll
            for (int i = 0; i < 8; i++)
#pragma unroll
                for (int j = 0; j < 4; j++) s[i][j] = 0.f;

#pragma unroll
            for (int kc = 0; kc < 4; kc++) {
                uint32_t qh_f[4], ql_f[4];
                ldmx4(qh_f, q_base + kc * 32);
                ldmx4(ql_f, q_base + AT_QLO + kc * 32);
                uint32_t koff = ((lane & 8) << 1) + kc * 32;
#pragma unroll
                for (int nt = 0; nt < 8; nt++) {
                    uint32_t ka = base + (nt * 8 + (lane & 7)) * AT_STRIDE + koff;
                    uint32_t bh[2], bl[2];
                    ldmx2(bh, ka);
                    ldmx2(bl, ka + AT_PLANE);
                    mma16816(s[nt], qh_f, bh);
                    mma16816(s[nt], qh_f, bl);
                    mma16816(s[nt], ql_f, bh);
                }
            }

            if (kt >= 2 * qt) {
#pragma unroll
                for (int nt = 0; nt < 8; nt++) {
                    int c = kt * 64 + nt * 8 + 2 * (lane & 3);
                    if (c     > row0)     s[nt][0] = -INFINITY;
                    if (c + 1 > row0)     s[nt][1] = -INFINITY;
                    if (c     > row0 + 8) s[nt][2] = -INFINITY;
                    if (c + 1 > row0 + 8) s[nt][3] = -INFINITY;
                }
            }

            float mx0 = -INFINITY, mx1 = -INFINITY;
#pragma unroll
            for (int nt = 0; nt < 8; nt++) {
                mx0 = fmaxf(mx0, fmaxf(s[nt][0], s[nt][1]));
                mx1 = fmaxf(mx1, fmaxf(s[nt][2], s[nt][3]));
            }
            mx0 = fmaxf(mx0, __shfl_xor_sync(0xffffffffu, mx0, 1));
            mx0 = fmaxf(mx0, __shfl_xor_sync(0xffffffffu, mx0, 2));
            mx1 = fmaxf(mx1, __shfl_xor_sync(0xffffffffu, mx1, 1));
            mx1 = fmaxf(mx1, __shfl_xor_sync(0xffffffffu, mx1, 2));
            float nm0 = fmaxf(m0, mx0), nm1 = fmaxf(m1, mx1);
            float a0 = __expf(m0 - nm0), a1 = __expf(m1 - nm1);
            m0 = nm0; m1 = nm1;
            float ps0 = 0.f, ps1 = 0.f;
#pragma unroll
            for (int nt = 0; nt < 8; nt++) {
                s[nt][0] = __expf(s[nt][0] - m0); ps0 += s[nt][0];
                s[nt][1] = __expf(s[nt][1] - m0); ps0 += s[nt][1];
                s[nt][2] = __expf(s[nt][2] - m1); ps1 += s[nt][2];
                s[nt][3] = __expf(s[nt][3] - m1); ps1 += s[nt][3];
            }
            l0 = l0 * a0 + ps0;
            l1 = l1 * a1 + ps1;
#pragma unroll
            for (int dt = 0; dt < 8; dt++) {
                oacc[dt][0] *= a0; oacc[dt][1] *= a0;
                oacc[dt][2] *= a1; oacc[dt][3] *= a1;
            }

#pragma unroll
            for (int kc = 0; kc < 4; kc++) {
                uint32_t ph[4], pl[4];
                packsplit(ph[0], pl[0], s[2 * kc][0],     s[2 * kc][1]);
                packsplit(ph[1], pl[1], s[2 * kc][2],     s[2 * kc][3]);
                packsplit(ph[2], pl[2], s[2 * kc + 1][0], s[2 * kc + 1][1]);
                packsplit(ph[3], pl[3], s[2 * kc + 1][2], s[2 * kc + 1][3]);
                uint32_t koff = ((lane & 8) << 1) + kc * 32;
#pragma unroll
                for (int dt = 0; dt < 8; dt++) {
                    uint32_t va = base + 2 * AT_PLANE + (dt * 8 + (lane & 7)) * AT_STRIDE + koff;
                    uint32_t vh[2], vl[2];
                    ldmx2(vh, va);
                    ldmx2(vl, va + AT_PLANE);
                    mma16816(oacc[dt], ph, vh);
                    mma16816(oacc[dt], ph, vl);
                    mma16816(oacc[dt], pl, vh);
                }
            }
        }
        __syncthreads();
        if (kt + 2 < ntiles) { at_load_tile(base, kh, kl, vth, vtl, head, kt + 2, tid); CP_COMMIT(); }
    }

    l0 += __shfl_xor_sync(0xffffffffu, l0, 1);
    l0 += __shfl_xor_sync(0xffffffffu, l0, 2);
    l1 += __shfl_xor_sync(0xffffffffu, l1, 1);
    l1 += __shfl_xor_sync(0xffffffffu, l1, 2);
    float i0 = 1.f / l0, i1 = 1.f / l1;
#pragma unroll
    for (int dt = 0; dt < 8; dt++) {
        int col = head * DH + dt * 8 + 2 * (lane & 3);
        uint32_t h0, lo0, h1, lo1;
        packsplit(h0, lo0, oacc[dt][0] * i0, oacc[dt][1] * i0);
        packsplit(h1, lo1, oacc[dt][2] * i1, oacc[dt][3] * i1);
        size_t i0x = (size_t)row0 * (D / 2) + (col >> 1);
        size_t i1x = (size_t)(row0 + 8) * (D / 2) + (col >> 1);
        ohp[i0x] = h0; olp[i0x] = lo0;
        ohp[i1x] = h1; olp[i1x] = lo1;
    }
}

// ---------------- out = x + b_mo + b_ao (float4) ----------------
__global__ void init_out_kernel(const float* __restrict__ x,
                                const float* __restrict__ bmo,
                                const float* __restrict__ bao,
                                float* __restrict__ out) {
    int i = blockIdx.x * blockDim.x + threadIdx.x;
    int col4 = i & (D / 4 - 1);
    float4 xv = ((const float4*)x)[i];
    float4 b0 = ((const float4*)bmo)[col4];
    float4 b1 = ((const float4*)bao)[col4];
    float4 o4;
    o4.x = xv.x + b0.x + b1.x;
    o4.y = xv.y + b0.y + b1.y;
    o4.z = xv.z + b0.z + b1.z;
    o4.w = xv.w + b0.w + b1.w;
    ((float4*)out)[i] = o4;
}

// ---------------- launch (simple 2-stream fork-join) ----------------
extern "C" void kernel_launch(void* const* d_in, const int* in_sizes, int n_in,
                              void* d_out, int out_size) {
    const float* x        = (const float*)d_in[0];
    // d_in[1] = mask (causal tril) handled analytically
    const float* ln_scale = (const float*)d_in[2];
    const float* ln_bias  = (const float*)d_in[3];
    const float* w_in     = (const float*)d_in[4];
    const float* b_in     = (const float*)d_in[5];
    const float* wq       = (const float*)d_in[6];
    const float* bq       = (const float*)d_in[7];
    const float* wk       = (const float*)d_in[8];
    const float* bk       = (const float*)d_in[9];
    const float* wv       = (const float*)d_in[10];
    const float* bv       = (const float*)d_in[11];
    const float* qn       = (const float*)d_in[12];
    const float* kn       = (const float*)d_in[13];
    const float* w_mo     = (const float*)d_in[14];
    const float* b_mo     = (const float*)d_in[15];
    const float* w_ao     = (const float*)d_in[16];
    const float* b_ao     = (const float*)d_in[17];
    float* out = (float*)d_out;

    float *q, *k, *v;
    cudaGetSymbolAddress((void**)&q, g_q);
    cudaGetSymbolAddress((void**)&k, g_k);
    cudaGetSymbolAddress((void**)&v, g_v);

    __nv_bfloat16 *xnh, *xnl, *wqkvh, *wqkvl, *oh, *ol, *waoh, *waol;
    __nv_bfloat16 *qsh, *qsl, *ksh, *ksl, *vth, *vtl;
    uint32_t *xnt, *wint, *ht, *wmot;
    cudaGetSymbolAddress((void**)&xnh, g_xnh);     cudaGetSymbolAddress((void**)&xnl, g_xnl);
    cudaGetSymbolAddress((void**)&xnt, g_xnt);
    cudaGetSymbolAddress((void**)&wqkvh, g_wqkvh); cudaGetSymbolAddress((void**)&wqkvl, g_wqkvl);
    cudaGetSymbolAddress((void**)&wint, g_wint);
    cudaGetSymbolAddress((void**)&ht, g_ht);
    cudaGetSymbolAddress((void**)&wmot, g_wmot);
    cudaGetSymbolAddress((void**)&oh, g_oh);       cudaGetSymbolAddress((void**)&ol, g_ol);
    cudaGetSymbolAddress((void**)&waoh, g_waoh);   cudaGetSymbolAddress((void**)&waol, g_waol);
    cudaGetSymbolAddress((void**)&qsh, g_qsh);     cudaGetSymbolAddress((void**)&qsl, g_qsl);
    cudaGetSymbolAddress((void**)&ksh, g_ksh);     cudaGetSymbolAddress((void**)&ksl, g_ksl);
    cudaGetSymbolAddress((void**)&vth, g_vth);     cudaGetSymbolAddress((void**)&vtl, g_vtl);

    cudaFuncSetAttribute(hmma_gemm_qkv, cudaFuncAttributeMaxDynamicSharedMemorySize, GSMEM);
    cudaFuncSetAttribute(hmma_gemm_acc, cudaFuncAttributeMaxDynamicSharedMemorySize, GSMEM);
    cudaFuncSetAttribute(tf32_gemm_h,   cudaFuncAttributeMaxDynamicSharedMemorySize, TF_SMEM);
    cudaFuncSetAttribute(tf32_gemm_acc, cudaFuncAttributeMaxDynamicSharedMemorySize, TF_SMEM);
    cudaFuncSetAttribute(hmma_attn,     cudaFuncAttributeMaxDynamicSharedMemorySize, AT_SMEM);

    static cudaStream_t side = nullptr;
    static cudaEvent_t ev_fork = nullptr, ev_ln = nullptr, ev_side = nullptr;
    if (!side) {
        cudaStreamCreateWithFlags(&side, cudaStreamNonBlocking);
        cudaEventCreateWithFlags(&ev_fork, cudaEventDisableTiming);
        cudaEventCreateWithFlags(&ev_ln,   cudaEventDisableTiming);
        cudaEventCreateWithFlags(&ev_side, cudaEventDisableTiming);
    }

    cudaEventRecord(ev_fork, 0);
    cudaStreamWaitEvent(side, ev_fork, 0);

    // side: tf32 weight packs + w_ao pack + out init, then (after LN) f1h -> w_mo
    splitT_tf32<<<dim3(F / 32, D / 32), dim3(32, 8), 0, side>>>(w_in, wint, D, F, D);
    splitT_tf32<<<dim3(D / 32, F / 32), dim3(32, 8), 0, side>>>(w_mo, wmot, F, D, F);
    splitT_kernel<<<dim3(D / 32, D / 32), dim3(32, 8), 0, side>>>(w_ao, waoh, waol, D, D, D);
    init_out_kernel<<<(S * D / 4) / 256, 256, 0, side>>>(x, b_mo, b_ao, out);

    // main: qkv weight packs, LN (records ev_ln)
    splitT_kernel<<<dim3(D / 32, D / 32), dim3(32, 8)>>>(wq, wqkvh, wqkvl, D, D, D);
    splitT_kernel<<<dim3(D / 32, D / 32), dim3(32, 8)>>>(wk, wqkvh + (size_t)D * D, wqkvl + (size_t)D * D, D, D, D);
    splitT_kernel<<<dim3(D / 32, D / 32), dim3(32, 8)>>>(wv, wqkvh + (size_t)2 * D * D, wqkvl + (size_t)2 * D * D, D, D, D);
    ln_split_kernel<<<S, 256>>>(x, ln_scale, ln_bias, (uint32_t*)xnh, (uint32_t*)xnl, xnt);
    cudaEventRecord(ev_ln, 0);

    // side: h = gelu(xn @ w_in) [tf32], then out += h @ w_mo [tf32]
    cudaStreamWaitEvent(side, ev_ln, 0);
    tf32_gemm_h<<<dim3(F / GBN, S / GBM), 256, TF_SMEM, side>>>(xnt, wint, b_in, ht);
    tf32_gemm_acc<<<dim3(D / GBN, S / GBM), 256, TF_SMEM, side>>>(ht, wmot, out);
    cudaEventRecord(ev_side, side);

    // main: qkv GEMM (bf16 3-term), qk-norm, V split-transpose, attention
    hmma_gemm_qkv<<<dim3(N3 / GBN, S / GBM), 256, GSMEM>>>(
        xnh, xnl, wqkvh, wqkvl, bq, bk, bv, q, k, v);
    qknorm_split2<<<(2 * S * H) / 256, 256>>>(q, k, qn, kn,
                                              (uint32_t*)qsh, (uint32_t*)qsl,
                                              (uint32_t*)ksh, (uint32_t*)ksl);
    splitT_kernel<<<dim3(D / 32, S / 32), dim3(32, 8)>>>(v, vth, vtl, S, D, S);
    hmma_attn<<<dim3(S / 128, H), 256, AT_SMEM>>>(qsh, qsl, ksh, ksl, vth, vtl,
                                                  (uint32_t*)oh, (uint32_t*)ol);

    // join, then out += o @ w_ao (bf16 3-term)
    cudaStreamWaitEvent(0, ev_side, 0);
    hmma_gemm_acc<<<dim3(D / GBN, S / GBM), 256, GSMEM>>>(
        oh, ol, waoh, waol, out, D, D, D, D);
}

// round 17
// speedup vs baseline: 1.7986x; 1.0047x over previous
#include <cuda_runtime.h>
#include <cuda_bf16.h>
#include <math.h>
#include <stdint.h>

#define S 4096
#define D 1024
#define H 16
#define DH 64
#define F 4096
#define N3 3072              // 3*D : QKV output width
#define EPSF 1e-6f

// ---------------- scratch (device globals: alloc-free) ----------------
__device__ float g_q [S * D];
__device__ float g_k [S * D];
__device__ float g_v [S * D];

__device__ __nv_bfloat16 g_xnh[S * D], g_xnl[S * D];       // LN output bf16 planes (qkv GEMM)
__device__ uint32_t      g_xnt[S * D];                     // LN output tf32 (h GEMM)
__device__ __nv_bfloat16 g_wqkvh[N3 * D], g_wqkvl[N3 * D]; // [wq|wk|wv]^T bf16 planes
__device__ uint32_t      g_wint[F * D];                    // w_in^T tf32 [F][D]
__device__ uint32_t      g_ht [S * F];                     // h tf32 [S][F]
__device__ uint32_t      g_wmot[D * F];                    // w_mo^T tf32 [D][F]
__device__ uint32_t      g_ot [S * D];                     // attention o tf32 [S][D]
__device__ uint32_t      g_waot[D * D];                    // w_ao^T tf32 [D][D]
__device__ __nv_bfloat16 g_qsh[S * D], g_qsl[S * D];       // q * 1/8 planes
__device__ __nv_bfloat16 g_ksh[S * D], g_ksl[S * D];       // k planes
__device__ uint32_t      g_vtt[D * S];                     // V^T tf32 [H*64 dims][S keys]

// ---------------- asm helpers (base sm_103 instructions) ----------------
__device__ __forceinline__ uint32_t smem_u32(const void* p) {
    uint32_t a;
    asm("{ .reg .u64 t; cvta.to.shared.u64 t, %1; cvt.u32.u64 %0, t; }" : "=r"(a) : "l"(p));
    return a;
}
__device__ __forceinline__ void cp16(uint32_t d, const void* s) {
    asm volatile("cp.async.cg.shared.global [%0], [%1], 16;" :: "r"(d), "l"(s));
}
#define CP_COMMIT() asm volatile("cp.async.commit_group;" ::: "memory")
#define CP_WAIT1()  asm volatile("cp.async.wait_group 1;" ::: "memory")
#define CP_WAIT0()  asm volatile("cp.async.wait_group 0;" ::: "memory")

__device__ __forceinline__ void ldmx4(uint32_t* r, uint32_t a) {
    asm volatile("ldmatrix.sync.aligned.m8n8.x4.shared.b16 {%0,%1,%2,%3}, [%4];"
                 : "=r"(r[0]), "=r"(r[1]), "=r"(r[2]), "=r"(r[3]) : "r"(a));
}
__device__ __forceinline__ void ldmx2(uint32_t* r, uint32_t a) {
    asm volatile("ldmatrix.sync.aligned.m8n8.x2.shared.b16 {%0,%1}, [%2];"
                 : "=r"(r[0]), "=r"(r[1]) : "r"(a));
}
__device__ __forceinline__ void mma16816(float* c, const uint32_t* a, const uint32_t* b) {
    asm volatile("mma.sync.aligned.m16n8k16.row.col.f32.bf16.bf16.f32 "
                 "{%0,%1,%2,%3}, {%4,%5,%6,%7}, {%8,%9}, {%0,%1,%2,%3};"
                 : "+f"(c[0]), "+f"(c[1]), "+f"(c[2]), "+f"(c[3])
                 : "r"(a[0]), "r"(a[1]), "r"(a[2]), "r"(a[3]), "r"(b[0]), "r"(b[1]));
}
__device__ __forceinline__ void mma_t32(float* c, const uint32_t* a, const uint32_t* b) {
    asm volatile("mma.sync.aligned.m16n8k8.row.col.f32.tf32.tf32.f32 "
                 "{%0,%1,%2,%3}, {%4,%5,%6,%7}, {%8,%9}, {%0,%1,%2,%3};"
                 : "+f"(c[0]), "+f"(c[1]), "+f"(c[2]), "+f"(c[3])
                 : "r"(a[0]), "r"(a[1]), "r"(a[2]), "r"(a[3]), "r"(b[0]), "r"(b[1]));
}
__device__ __forceinline__ uint32_t to_tf32(float x) {
    uint32_t u;
    asm("cvt.rna.tf32.f32 %0, %1;" : "=r"(u) : "f"(x));
    return u;
}

__device__ __forceinline__ float gelu_f(float x) {
    float x3 = x * x * x;
    return 0.5f * x * (1.f + tanhf(0.7978845608028654f * (x + 0.044715f * x3)));
}

__device__ __forceinline__ void packsplit(uint32_t& hi, uint32_t& lo, float a, float b) {
    __nv_bfloat162 h = __floats2bfloat162_rn(a, b);
    float r0 = a - __bfloat162float(__low2bfloat16(h));
    float r1 = b - __bfloat162float(__high2bfloat16(h));
    __nv_bfloat162 l = __floats2bfloat162_rn(r0, r1);
    hi = *reinterpret_cast<uint32_t*>(&h);
    lo = *reinterpret_cast<uint32_t*>(&l);
}

// ---------------- split-transpose (bf16 hi/lo): [Kd][Nd] fp32 -> [n][k] ----------------
__global__ void splitT_kernel(const float* __restrict__ in,
                              __nv_bfloat16* __restrict__ hi,
                              __nv_bfloat16* __restrict__ lo,
                              int Kd, int Nd, int ostride) {
    __shared__ float t[32][33];
    int n0 = blockIdx.x * 32, k0 = blockIdx.y * 32;
    int tx = threadIdx.x, ty = threadIdx.y;
#pragma unroll
    for (int j = 0; j < 4; j++)
        t[ty + j * 8][tx] = in[(size_t)(k0 + ty + j * 8) * Nd + n0 + tx];
    __syncthreads();
#pragma unroll
    for (int j = 0; j < 4; j++) {
        float v = t[tx][ty + j * 8];
        int n = n0 + ty + j * 8, k = k0 + tx;
        __nv_bfloat16 h = __float2bfloat16(v);
        hi[(size_t)n * ostride + k] = h;
        lo[(size_t)n * ostride + k] = __float2bfloat16(v - __bfloat162float(h));
    }
}

// ---------------- transpose to tf32: [Kd][Nd] fp32 -> [n][k] tf32 ----------------
__global__ void splitT_tf32(const float* __restrict__ in,
                            uint32_t* __restrict__ out,
                            int Kd, int Nd, int ostride) {
    __shared__ float t[32][33];
    int n0 = blockIdx.x * 32, k0 = blockIdx.y * 32;
    int tx = threadIdx.x, ty = threadIdx.y;
#pragma unroll
    for (int j = 0; j < 4; j++)
        t[ty + j * 8][tx] = in[(size_t)(k0 + ty + j * 8) * Nd + n0 + tx];
    __syncthreads();
#pragma unroll
    for (int j = 0; j < 4; j++) {
        int n = n0 + ty + j * 8, k = k0 + tx;
        out[(size_t)n * ostride + k] = to_tf32(t[tx][ty + j * 8]);
    }
}

// ---------------- LayerNorm + split (bf16 planes + tf32 plane) ----------------
__global__ void ln_split_kernel(const float* __restrict__ x,
                                const float* __restrict__ gamma,
                                const float* __restrict__ beta,
                                uint32_t* __restrict__ yh,
                                uint32_t* __restrict__ yl,
                                uint32_t* __restrict__ yt) {
    __shared__ float sh[8];
    __shared__ float stat;
    int row = blockIdx.x;
    int t = threadIdx.x;
    float4 xv = ((const float4*)(x + (size_t)row * D))[t];

    float s = xv.x + xv.y + xv.z + xv.w;
#pragma unroll
    for (int o = 16; o > 0; o >>= 1) s += __shfl_xor_sync(0xffffffffu, s, o);
    if ((t & 31) == 0) sh[t >> 5] = s;
    __syncthreads();
    if (t == 0) {
        float tot = 0.f;
#pragma unroll
        for (int i = 0; i < 8; i++) tot += sh[i];
        stat = tot * (1.f / (float)D);
    }
    __syncthreads();
    float mean = stat;

    float d0 = xv.x - mean, d1 = xv.y - mean, d2 = xv.z - mean, d3 = xv.w - mean;
    float sq = d0 * d0 + d1 * d1 + d2 * d2 + d3 * d3;
#pragma unroll
    for (int o = 16; o > 0; o >>= 1) sq += __shfl_xor_sync(0xffffffffu, sq, o);
    __syncthreads();
    if ((t & 31) == 0) sh[t >> 5] = sq;
    __syncthreads();
    if (t == 0) {
        float tot = 0.f;
#pragma unroll
        for (int i = 0; i < 8; i++) tot += sh[i];
        stat = rsqrtf(tot * (1.f / (float)D) + EPSF);
    }
    __syncthreads();
    float rinv = stat;

    float4 gv = ((const float4*)gamma)[t];
    float4 bv = ((const float4*)beta)[t];
    float v0 = d0 * rinv * gv.x + bv.x;
    float v1 = d1 * rinv * gv.y + bv.y;
    float v2 = d2 * rinv * gv.z + bv.z;
    float v3 = d3 * rinv * gv.w + bv.w;
    uint32_t h0, l0, h1, l1;
    packsplit(h0, l0, v0, v1);
    packsplit(h1, l1, v2, v3);
    int idx = row * (D / 2) + 2 * t;
    yh[idx] = h0; yh[idx + 1] = h1;
    yl[idx] = l0; yl[idx + 1] = l1;
    uint4 tv = {to_tf32(v0), to_tf32(v1), to_tf32(v2), to_tf32(v3)};
    ((uint4*)yt)[row * (D / 4) + t] = tv;
}

// ---------------- fused per-head LN + scale + split for q AND k ----------------
__global__ void qknorm_split2(const float* __restrict__ qin, const float* __restrict__ kin,
                              const float* __restrict__ qscale, const float* __restrict__ kscale,
                              uint32_t* __restrict__ qoh, uint32_t* __restrict__ qol,
                              uint32_t* __restrict__ koh, uint32_t* __restrict__ kol) {
    int gid = blockIdx.x * blockDim.x + threadIdx.x;
    int is_k = gid >= S * H;
    int row = is_k ? gid - S * H : gid;
    const float* p = (is_k ? kin : qin) + (size_t)row * DH;
    const float* scale = is_k ? kscale : qscale;
    uint32_t* oh = is_k ? koh : qoh;
    uint32_t* ol = is_k ? kol : qol;
    float sc = is_k ? 1.f : 0.125f;

    float4 v[16];
    float s = 0.f;
#pragma unroll
    for (int i = 0; i < 16; i++) {
        v[i] = ((const float4*)p)[i];
        s += v[i].x + v[i].y + v[i].z + v[i].w;
    }
    float mean = s * (1.f / (float)DH);
    float sq = 0.f;
#pragma unroll
    for (int i = 0; i < 16; i++) {
        v[i].x -= mean; v[i].y -= mean; v[i].z -= mean; v[i].w -= mean;
        sq += v[i].x * v[i].x + v[i].y * v[i].y + v[i].z * v[i].z + v[i].w * v[i].w;
    }
    float r = rsqrtf(sq * (1.f / (float)DH) + EPSF) * sc;
#pragma unroll
    for (int i = 0; i < 16; i++) {
        float4 scv = ((const float4*)scale)[i];
        uint32_t h0, l0, h1, l1;
        packsplit(h0, l0, v[i].x * r * scv.x, v[i].y * r * scv.y);
        packsplit(h1, l1, v[i].z * r * scv.z, v[i].w * r * scv.w);
        int idx = row * (DH / 2) + 2 * i;
        oh[idx] = h0; oh[idx + 1] = h1;
        ol[idx] = l0; ol[idx + 1] = l1;
    }
}

// ================= bf16 3-term HMMA GEMM core =================
#define GBM 128
#define GBN 128
#define GBK 32
#define PLANE_B (128 * 40 * 2)
#define BUF_B   (4 * PLANE_B)
#define GSMEM   (2 * BUF_B)

__device__ __forceinline__ void issue_chunk(
    uint32_t base,
    const __nv_bfloat16* Ah, const __nv_bfloat16* Al,
    const __nv_bfloat16* Bh, const __nv_bfloat16* Bl,
    int bm, int bn, int kc, int lda, int ldb, int tid)
{
    int row  = tid >> 1;
    int half = tid & 1;
    uint32_t doff = row * 80 + half * 32;
    size_t aoff = (size_t)(bm + row) * lda + kc + half * 16;
    size_t boff = (size_t)(bn + row) * ldb + kc + half * 16;
    cp16(base + doff,                    Ah + aoff);
    cp16(base + doff + 16,               Ah + aoff + 8);
    cp16(base + PLANE_B + doff,          Al + aoff);
    cp16(base + PLANE_B + doff + 16,     Al + aoff + 8);
    cp16(base + 2 * PLANE_B + doff,      Bh + boff);
    cp16(base + 2 * PLANE_B + doff + 16, Bh + boff + 8);
    cp16(base + 3 * PLANE_B + doff,      Bl + boff);
    cp16(base + 3 * PLANE_B + doff + 16, Bl + boff + 8);
}

__device__ __forceinline__ void hmma_mainloop(
    uint32_t sb, float acc[4][4][4],
    const __nv_bfloat16* Ah, const __nv_bfloat16* Al,
    const __nv_bfloat16* Bh, const __nv_bfloat16* Bl,
    int bm, int bn, int K, int lda, int ldb, int tid, int lane, int wm, int wn)
{
    uint32_t a_off = (uint32_t)((wm * 64 + (lane & 7) + (lane & 8)) * 80 + ((lane >> 4) << 4));
    uint32_t b_off = (uint32_t)((wn * 32 + (lane & 7)) * 80 + ((lane & 8) << 1));

    int nk = K / GBK;
    issue_chunk(sb, Ah, Al, Bh, Bl, bm, bn, 0, lda, ldb, tid);
    CP_COMMIT();

    for (int c = 0; c < nk; c++) {
        CP_WAIT0();
        __syncthreads();
        if (c + 1 < nk) {
            issue_chunk(sb + ((c + 1) & 1) * BUF_B, Ah, Al, Bh, Bl, bm, bn, (c + 1) * GBK, lda, ldb, tid);
            CP_COMMIT();
        }
        uint32_t base = sb + (c & 1) * BUF_B;
        uint32_t aH = base, aL = base + PLANE_B;
        uint32_t bH = base + 2 * PLANE_B, bL = base + 3 * PLANE_B;

#pragma unroll
        for (int k16 = 0; k16 < 2; k16++) {
            uint32_t kb = k16 * 32;
            uint32_t ahf[4][4], bfr[4][2];
#pragma unroll
            for (int mt = 0; mt < 4; mt++) ldmx4(ahf[mt], aH + a_off + mt * 1280 + kb);
#pragma unroll
            for (int nt = 0; nt < 4; nt++) ldmx2(bfr[nt], bH + b_off + nt * 640 + kb);
#pragma unroll
            for (int mt = 0; mt < 4; mt++)
#pragma unroll
                for (int nt = 0; nt < 4; nt++) mma16816(acc[mt][nt], ahf[mt], bfr[nt]);

            uint32_t alf[4][4];
#pragma unroll
            for (int mt = 0; mt < 4; mt++) ldmx4(alf[mt], aL + a_off + mt * 1280 + kb);
#pragma unroll
            for (int mt = 0; mt < 4; mt++)
#pragma unroll
                for (int nt = 0; nt < 4; nt++) mma16816(acc[mt][nt], alf[mt], bfr[nt]);

#pragma unroll
            for (int nt = 0; nt < 4; nt++) ldmx2(bfr[nt], bL + b_off + nt * 640 + kb);
#pragma unroll
            for (int mt = 0; mt < 4; mt++)
#pragma unroll
                for (int nt = 0; nt < 4; nt++) mma16816(acc[mt][nt], ahf[mt], bfr[nt]);
        }
    }
}

// ================= tf32 1-term GEMM core =================
#define TF_STRIDE 144
#define TF_PLANE (128 * TF_STRIDE)
#define TF_BUF   (2 * TF_PLANE)
#define TF_SMEM  (2 * TF_BUF)

__device__ __forceinline__ void issue_chunk_t(
    uint32_t base, const uint32_t* A, const uint32_t* B,
    int bm, int bn, int kc, int lda, int ldb, int tid)
{
    int row = tid >> 1, half = tid & 1;
    uint32_t doff = row * TF_STRIDE + half * 64;
    size_t aoff = (size_t)(bm + row) * lda + kc + half * 16;
    size_t boff = (size_t)(bn + row) * ldb + kc + half * 16;
    cp16(base + doff,      A + aoff);
    cp16(base + doff + 16, A + aoff + 4);
    cp16(base + doff + 32, A + aoff + 8);
    cp16(base + doff + 48, A + aoff + 12);
    uint32_t d2 = base + TF_PLANE + doff;
    cp16(d2,      B + boff);
    cp16(d2 + 16, B + boff + 4);
    cp16(d2 + 32, B + boff + 8);
    cp16(d2 + 48, B + boff + 12);
}

__device__ __forceinline__ void tf32_mainloop(
    uint32_t sb, float acc[4][4][4],
    const uint32_t* A, const uint32_t* B,
    int bm, int bn, int K, int lda, int ldb, int tid, int lane, int wm, int wn)
{
    uint32_t a_off = (uint32_t)((wm * 64 + (lane & 7) + (lane & 8)) * TF_STRIDE + ((lane >> 4) << 4));
    uint32_t b_off = (uint32_t)((wn * 32 + (lane & 7)) * TF_STRIDE + ((lane & 8) << 1));

    int nk = K / GBK;
    issue_chunk_t(sb, A, B, bm, bn, 0, lda, ldb, tid);
    CP_COMMIT();

    for (int c = 0; c < nk; c++) {
        CP_WAIT0();
        __syncthreads();
        if (c + 1 < nk) {
            issue_chunk_t(sb + ((c + 1) & 1) * TF_BUF, A, B, bm, bn, (c + 1) * GBK, lda, ldb, tid);
            CP_COMMIT();
        }
        uint32_t base = sb + (c & 1) * TF_BUF;
        uint32_t aP = base, bP = base + TF_PLANE;

#pragma unroll
        for (int k8 = 0; k8 < 4; k8++) {
            uint32_t kb = k8 * 32;
            uint32_t af[4][4], bf[4][2];
#pragma unroll
            for (int mt = 0; mt < 4; mt++) ldmx4(af[mt], aP + a_off + mt * 16 * TF_STRIDE + kb);
#pragma unroll
            for (int nt = 0; nt < 4; nt++) ldmx2(bf[nt], bP + b_off + nt * 8 * TF_STRIDE + kb);
#pragma unroll
            for (int mt = 0; mt < 4; mt++)
#pragma unroll
                for (int nt = 0; nt < 4; nt++) mma_t32(acc[mt][nt], af[mt], bf[nt]);
        }
    }
}

// ---- f1qkv (bf16): [q|k|v] = xn @ [wq|wk|wv]^T + bias ----
__global__ void __launch_bounds__(256, 2) hmma_gemm_qkv(
    const __nv_bfloat16* __restrict__ Ah, const __nv_bfloat16* __restrict__ Al,
    const __nv_bfloat16* __restrict__ Bh, const __nv_bfloat16* __restrict__ Bl,
    const float* __restrict__ bq, const float* __restrict__ bk, const float* __restrict__ bv,
    float* __restrict__ qf, float* __restrict__ kf, float* __restrict__ vf)
{
    extern __shared__ __align__(128) char smem[];
    uint32_t sb = smem_u32(smem);
    int tid = threadIdx.x, lane = tid & 31, wid = tid >> 5;
    int wm = wid >> 2, wn = wid & 3;
    int bm = blockIdx.y * GBM, bn = blockIdx.x * GBN;

    float acc[4][4][4];
#pragma unroll
    for (int i = 0; i < 4; i++)
#pragma unroll
        for (int j = 0; j < 4; j++)
#pragma unroll
            for (int r = 0; r < 4; r++) acc[i][j][r] = 0.f;

    hmma_mainloop(sb, acc, Ah, Al, Bh, Bl, bm, bn, D, D, D, tid, lane, wm, wn);

    int lr = lane >> 2, lc = (lane & 3) * 2;
#pragma unroll
    for (int mt = 0; mt < 4; mt++) {
#pragma unroll
        for (int nt = 0; nt < 4; nt++) {
            float* a = acc[mt][nt];
            int m0 = bm + wm * 64 + mt * 16 + lr;
            int n0 = bn + wn * 32 + nt * 8 + lc;
            int r = n0 >> 10;
            int c = n0 & (D - 1);
            const float* bp = (r == 0) ? bq : (r == 1) ? bk : bv;
            float* dst = (r == 0) ? qf : (r == 1) ? kf : vf;
            float b0 = bp[c], b1 = bp[c + 1];
            float2 w0 = {a[0] + b0, a[1] + b1};
            float2 w1 = {a[2] + b0, a[3] + b1};
            *(float2*)(dst + (size_t)m0 * D + c) = w0;
            *(float2*)(dst + (size_t)(m0 + 8) * D + c) = w1;
        }
    }
}

// ---- f1h (tf32): h = gelu(xn_t @ w_in^T + b_in), stored tf32 ----
__global__ void __launch_bounds__(256, 2) tf32_gemm_h(
    const uint32_t* __restrict__ A, const uint32_t* __restrict__ B,
    const float* __restrict__ b_in, uint32_t* __restrict__ ht)
{
    extern __shared__ __align__(128) char smem[];
    uint32_t sb = smem_u32(smem);
    int tid = threadIdx.x, lane = tid & 31, wid = tid >> 5;
    int wm = wid >> 2, wn = wid & 3;
    int bm = blockIdx.y * GBM, bn = blockIdx.x * GBN;

    float acc[4][4][4];
#pragma unroll
    for (int i = 0; i < 4; i++)
#pragma unroll
        for (int j = 0; j < 4; j++)
#pragma unroll
            for (int r = 0; r < 4; r++) acc[i][j][r] = 0.f;

    tf32_mainloop(sb, acc, A, B, bm, bn, D, D, D, tid, lane, wm, wn);

    int lr = lane >> 2, lc = (lane & 3) * 2;
#pragma unroll
    for (int mt = 0; mt < 4; mt++) {
#pragma unroll
        for (int nt = 0; nt < 4; nt++) {
            float* a = acc[mt][nt];
            int m0 = bm + wm * 64 + mt * 16 + lr;
            int n0 = bn + wn * 32 + nt * 8 + lc;
            float b0 = b_in[n0], b1 = b_in[n0 + 1];
            uint2 w0 = {to_tf32(gelu_f(a[0] + b0)), to_tf32(gelu_f(a[1] + b1))};
            uint2 w1 = {to_tf32(gelu_f(a[2] + b0)), to_tf32(gelu_f(a[3] + b1))};
            *(uint2*)(ht + (size_t)m0 * F + n0) = w0;
            *(uint2*)(ht + (size_t)(m0 + 8) * F + n0) = w1;
        }
    }
}

// ---- tf32 accumulate GEMM: C += A @ B^T (strided) ----
__global__ void __launch_bounds__(256, 2) tf32_gemm_acc(
    const uint32_t* __restrict__ A, const uint32_t* __restrict__ B,
    float* __restrict__ C, int N, int K, int lda, int ldb)
{
    extern __shared__ __align__(128) char smem[];
    uint32_t sb = smem_u32(smem);
    int tid = threadIdx.x, lane = tid & 31, wid = tid >> 5;
    int wm = wid >> 2, wn = wid & 3;
    int bm = blockIdx.y * GBM, bn = blockIdx.x * GBN;

    float acc[4][4][4];
#pragma unroll
    for (int i = 0; i < 4; i++)
#pragma unroll
        for (int j = 0; j < 4; j++)
#pragma unroll
            for (int r = 0; r < 4; r++) acc[i][j][r] = 0.f;

    tf32_mainloop(sb, acc, A, B, bm, bn, K, lda, ldb, tid, lane, wm, wn);

    int lr = lane >> 2, lc = (lane & 3) * 2;
#pragma unroll
    for (int mt = 0; mt < 4; mt++) {
#pragma unroll
        for (int nt = 0; nt < 4; nt++) {
            float* a = acc[mt][nt];
            int m0 = bm + wm * 64 + mt * 16 + lr;
            int n0 = bn + wn * 32 + nt * 8 + lc;
            float2* p0 = (float2*)(C + (size_t)m0 * N + n0);
            float2* p1 = (float2*)(C + (size_t)(m0 + 8) * N + n0);
            float2 v0 = *p0, v1 = *p1;
            v0.x += a[0]; v0.y += a[1];
            v1.x += a[2]; v1.y += a[3];
            *p0 = v0; *p1 = v1;
        }
    }
}

// ================= HMMA flash attention: QK bf16 3-term, PV tf32 1-term =================
#define AT_STRIDE 144
#define AT_PLANE (64 * AT_STRIDE)       // 9216 B (K hi / K lo planes)
#define AT_VSTRIDE 272                  // 64 tf32 + 16 B pad (phase-preserving)
#define AT_VPLANE (64 * AT_VSTRIDE)     // 17408 B (V tf32 plane)
#define AT_BUF   (2 * AT_PLANE + AT_VPLANE)   // 35840 B
#define AT_QOFF  (2 * AT_BUF)                 // 71680
#define AT_QLO   (128 * AT_STRIDE)            // 18432
#define AT_SMEM  (AT_QOFF + 2 * AT_QLO)       // 108544 B, 2 CTAs/SM

__device__ __forceinline__ void at_load_tile(
    uint32_t dst, const __nv_bfloat16* kh, const __nv_bfloat16* kl,
    const uint32_t* vtt, int head, int kt, int tid)
{
    int row = tid >> 2, q4 = tid & 3;
    size_t koff = (size_t)(kt * 64 + row) * D + head * DH + q4 * 16;
    uint32_t d = dst + row * AT_STRIDE + q4 * 32;
    cp16(d,                 kh + koff);
    cp16(d + 16,            kh + koff + 8);
    cp16(d + AT_PLANE,      kl + koff);
    cp16(d + AT_PLANE + 16, kl + koff + 8);
    // V tf32: row = dim (0..63), 4 threads/row x 64 B (16 keys)
    size_t voff = (size_t)(head * DH + row) * S + kt * 64 + q4 * 16;
    uint32_t dv = dst + 2 * AT_PLANE + row * AT_VSTRIDE + q4 * 64;
    cp16(dv,      vtt + voff);
    cp16(dv + 16, vtt + voff + 4);
    cp16(dv + 32, vtt + voff + 8);
    cp16(dv + 48, vtt + voff + 12);
}

__global__ void __launch_bounds__(256, 2) hmma_attn(
    const __nv_bfloat16* __restrict__ qh, const __nv_bfloat16* __restrict__ ql,
    const __nv_bfloat16* __restrict__ kh, const __nv_bfloat16* __restrict__ kl,
    const uint32_t* __restrict__ vtt, uint32_t* __restrict__ ot)
{
    extern __shared__ __align__(128) char smem[];
    uint32_t sb = smem_u32(smem);
    int tid = threadIdx.x, lane = tid & 31, wid = tid >> 5;
    int qt = (int)gridDim.x - 1 - (int)blockIdx.x;   // heavy tiles first
    int head = blockIdx.y;
    int ntiles = 2 * qt + 2;

    {
        int row = tid >> 1, half = tid & 1;
        const __nv_bfloat16* s0 = qh + (size_t)(qt * 128 + row) * D + head * DH + half * 32;
        const __nv_bfloat16* s1 = ql + (size_t)(qt * 128 + row) * D + head * DH + half * 32;
        uint32_t dq = sb + AT_QOFF + row * AT_STRIDE + half * 64;
        cp16(dq,      s0); cp16(dq + 16, s0 + 8);
        cp16(dq + 32, s0 + 16); cp16(dq + 48, s0 + 24);
        uint32_t dl = dq + AT_QLO;
        cp16(dl,      s1); cp16(dl + 16, s1 + 8);
        cp16(dl + 32, s1 + 16); cp16(dl + 48, s1 + 24);
    }
    CP_COMMIT();
    at_load_tile(sb, kh, kl, vtt, head, 0, tid);
    CP_COMMIT();
    if (ntiles > 1) { at_load_tile(sb + AT_BUF, kh, kl, vtt, head, 1, tid); CP_COMMIT(); }

    float oacc[8][4];
#pragma unroll
    for (int i = 0; i < 8; i++)
#pragma unroll
        for (int j = 0; j < 4; j++) oacc[i][j] = 0.f;
    float m0 = -INFINITY, m1 = -INFINITY, l0 = 0.f, l1 = 0.f;
    int row0 = qt * 128 + wid * 16 + (lane >> 2);
    uint32_t q_base = sb + AT_QOFF + (wid * 16 + (lane & 15)) * AT_STRIDE + ((lane >> 4) & 1) * 16;

    for (int kt = 0; kt < ntiles; kt++) {
        if (kt + 1 < ntiles) CP_WAIT1(); else CP_WAIT0();
        __syncthreads();
        uint32_t base = sb + (kt & 1) * AT_BUF;

        if (kt * 64 <= qt * 128 + wid * 16 + 15) {
            float s[8][4];
#pragma unroll
            for (int i = 0; i < 8; i++)
#pragma unroll
                for (int j = 0; j < 4; j++) s[i][j] = 0.f;

            // S = Q @ K^T (bf16 3-term)
#pragma unroll
            for (int kc = 0; kc < 4; kc++) {
                uint32_t qh_f[4], ql_f[4];
                ldmx4(qh_f, q_base + kc * 32);
                ldmx4(ql_f, q_base + AT_QLO + kc * 32);
                uint32_t koff = ((lane & 8) << 1) + kc * 32;
#pragma unroll
                for (int nt = 0; nt < 8; nt++) {
                    uint32_t ka = base + (nt * 8 + (lane & 7)) * AT_STRIDE + koff;
                    uint32_t bh[2], bl[2];
                    ldmx2(bh, ka);
                    ldmx2(bl, ka + AT_PLANE);
                    mma16816(s[nt], qh_f, bh);
                    mma16816(s[nt], qh_f, bl);
                    mma16816(s[nt], ql_f, bh);
                }
            }

            if (kt >= 2 * qt) {
#pragma unroll
                for (int nt = 0; nt < 8; nt++) {
                    int c = kt * 64 + nt * 8 + 2 * (lane & 3);
                    if (c     > row0)     s[nt][0] = -INFINITY;
                    if (c + 1 > row0)     s[nt][1] = -INFINITY;
                    if (c     > row0 + 8) s[nt][2] = -INFINITY;
                    if (c + 1 > row0 + 8) s[nt][3] = -INFINITY;
                }
            }

            float mx0 = -INFINITY, mx1 = -INFINITY;
#pragma unroll
            for (int nt = 0; nt < 8; nt++) {
                mx0 = fmaxf(mx0, fmaxf(s[nt][0], s[nt][1]));
                mx1 = fmaxf(mx1, fmaxf(s[nt][2], s[nt][3]));
            }
            mx0 = fmaxf(mx0, __shfl_xor_sync(0xffffffffu, mx0, 1));
            mx0 = fmaxf(mx0, __shfl_xor_sync(0xffffffffu, mx0, 2));
            mx1 = fmaxf(mx1, __shfl_xor_sync(0xffffffffu, mx1, 1));
            mx1 = fmaxf(mx1, __shfl_xor_sync(0xffffffffu, mx1, 2));
            float nm0 = fmaxf(m0, mx0), nm1 = fmaxf(m1, mx1);
            float a0 = __expf(m0 - nm0), a1 = __expf(m1 - nm1);
            m0 = nm0; m1 = nm1;
            float ps0 = 0.f, ps1 = 0.f;
#pragma unroll
            for (int nt = 0; nt < 8; nt++) {
                s[nt][0] = __expf(s[nt][0] - m0); ps0 += s[nt][0];
                s[nt][1] = __expf(s[nt][1] - m0); ps0 += s[nt][1];
                s[nt][2] = __expf(s[nt][2] - m1); ps1 += s[nt][2];
                s[nt][3] = __expf(s[nt][3] - m1); ps1 += s[nt][3];
            }
            l0 = l0 * a0 + ps0;
            l1 = l1 * a1 + ps1;
#pragma unroll
            for (int dt = 0; dt < 8; dt++) {
                oacc[dt][0] *= a0; oacc[dt][1] *= a0;
                oacc[dt][2] *= a1; oacc[dt][3] *= a1;
            }

            // O += P @ V (tf32 1-term). P C-layout -> tf32 A-frag via quad shuffles.
#pragma unroll
            for (int nt = 0; nt < 8; nt++) {
                int src0 = (lane & ~3) | ((lane & 3) >> 1);
                int src1 = src0 + 2;
                float t00 = __shfl_sync(0xffffffffu, s[nt][0], src0);
                float t01 = __shfl_sync(0xffffffffu, s[nt][1], src0);
                float t10 = __shfl_sync(0xffffffffu, s[nt][2], src0);
                float t11 = __shfl_sync(0xffffffffu, s[nt][3], src0);
                float t20 = __shfl_sync(0xffffffffu, s[nt][0], src1);
                float t21 = __shfl_sync(0xffffffffu, s[nt][1], src1);
                float t30 = __shfl_sync(0xffffffffu, s[nt][2], src1);
                float t31 = __shfl_sync(0xffffffffu, s[nt][3], src1);
                bool odd = lane & 1;
                uint32_t pa[4];
                pa[0] = to_tf32(odd ? t01 : t00);
                pa[1] = to_tf32(odd ? t11 : t10);
                pa[2] = to_tf32(odd ? t21 : t20);
                pa[3] = to_tf32(odd ? t31 : t30);
                uint32_t kb = (uint32_t)nt * 32;   // 8 keys * 4 B
#pragma unroll
                for (int dt = 0; dt < 8; dt++) {
                    uint32_t va = base + 2 * AT_PLANE + (dt * 8 + (lane & 7)) * AT_VSTRIDE
                                + ((lane & 8) << 1) + kb;
                    uint32_t vf[2];
                    ldmx2(vf, va);
                    mma_t32(oacc[dt], pa, vf);
                }
            }
        }
        __syncthreads();
        if (kt + 2 < ntiles) { at_load_tile(base, kh, kl, vtt, head, kt + 2, tid); CP_COMMIT(); }
    }

    l0 += __shfl_xor_sync(0xffffffffu, l0, 1);
    l0 += __shfl_xor_sync(0xffffffffu, l0, 2);
    l1 += __shfl_xor_sync(0xffffffffu, l1, 1);
    l1 += __shfl_xor_sync(0xffffffffu, l1, 2);
    float i0 = 1.f / l0, i1 = 1.f / l1;
#pragma unroll
    for (int dt = 0; dt < 8; dt++) {
        int col = head * DH + dt * 8 + 2 * (lane & 3);
        uint2 w0 = {to_tf32(oacc[dt][0] * i0), to_tf32(oacc[dt][1] * i0)};
        uint2 w1 = {to_tf32(oacc[dt][2] * i1), to_tf32(oacc[dt][3] * i1)};
        *(uint2*)(ot + (size_t)row0 * D + col) = w0;
        *(uint2*)(ot + (size_t)(row0 + 8) * D + col) = w1;
    }
}

// ---------------- out = x + b_mo + b_ao (float4) ----------------
__global__ void init_out_kernel(const float* __restrict__ x,
                                const float* __restrict__ bmo,
                                const float* __restrict__ bao,
                                float* __restrict__ out) {
    int i = blockIdx.x * blockDim.x + threadIdx.x;
    int col4 = i & (D / 4 - 1);
    float4 xv = ((const float4*)x)[i];
    float4 b0 = ((const float4*)bmo)[col4];
    float4 b1 = ((const float4*)bao)[col4];
    float4 o4;
    o4.x = xv.x + b0.x + b1.x;
    o4.y = xv.y + b0.y + b1.y;
    o4.z = xv.z + b0.z + b1.z;
    o4.w = xv.w + b0.w + b1.w;
    ((float4*)out)[i] = o4;
}

// ---------------- launch (2-stream fork-join) ----------------
extern "C" void kernel_launch(void* const* d_in, const int* in_sizes, int n_in,
                              void* d_out, int out_size) {
    const float* x        = (const float*)d_in[0];
    // d_in[1] = mask (causal tril) handled analytically
    const float* ln_scale = (const float*)d_in[2];
    const float* ln_bias  = (const float*)d_in[3];
    const float* w_in     = (const float*)d_in[4];
    const float* b_in     = (const float*)d_in[5];
    const float* wq       = (const float*)d_in[6];
    const float* bq       = (const float*)d_in[7];
    const float* wk       = (const float*)d_in[8];
    const float* bk       = (const float*)d_in[9];
    const float* wv       = (const float*)d_in[10];
    const float* bv       = (const float*)d_in[11];
    const float* qn       = (const float*)d_in[12];
    const float* kn       = (const float*)d_in[13];
    const float* w_mo     = (const float*)d_in[14];
    const float* b_mo     = (const float*)d_in[15];
    const float* w_ao     = (const float*)d_in[16];
    const float* b_ao     = (const float*)d_in[17];
    float* out = (float*)d_out;

    float *q, *k, *v;
    cudaGetSymbolAddress((void**)&q, g_q);
    cudaGetSymbolAddress((void**)&k, g_k);
    cudaGetSymbolAddress((void**)&v, g_v);

    __nv_bfloat16 *xnh, *xnl, *wqkvh, *wqkvl, *qsh, *qsl, *ksh, *ksl;
    uint32_t *xnt, *wint, *ht, *wmot, *ot, *waot, *vtt;
    cudaGetSymbolAddress((void**)&xnh, g_xnh);     cudaGetSymbolAddress((void**)&xnl, g_xnl);
    cudaGetSymbolAddress((void**)&xnt, g_xnt);
    cudaGetSymbolAddress((void**)&wqkvh, g_wqkvh); cudaGetSymbolAddress((void**)&wqkvl, g_wqkvl);
    cudaGetSymbolAddress((void**)&wint, g_wint);
    cudaGetSymbolAddress((void**)&ht, g_ht);
    cudaGetSymbolAddress((void**)&wmot, g_wmot);
    cudaGetSymbolAddress((void**)&ot, g_ot);
    cudaGetSymbolAddress((void**)&waot, g_waot);
    cudaGetSymbolAddress((void**)&qsh, g_qsh);     cudaGetSymbolAddress((void**)&qsl, g_qsl);
    cudaGetSymbolAddress((void**)&ksh, g_ksh);     cudaGetSymbolAddress((void**)&ksl, g_ksl);
    cudaGetSymbolAddress((void**)&vtt, g_vtt);

    cudaFuncSetAttribute(hmma_gemm_qkv, cudaFuncAttributeMaxDynamicSharedMemorySize, GSMEM);
    cudaFuncSetAttribute(tf32_gemm_h,   cudaFuncAttributeMaxDynamicSharedMemorySize, TF_SMEM);
    cudaFuncSetAttribute(tf32_gemm_acc, cudaFuncAttributeMaxDynamicSharedMemorySize, TF_SMEM);
    cudaFuncSetAttribute(hmma_attn,     cudaFuncAttributeMaxDynamicSharedMemorySize, AT_SMEM);

    static cudaStream_t side = nullptr;
    static cudaEvent_t ev_fork = nullptr, ev_ln = nullptr, ev_side = nullptr;
    if (!side) {
        cudaStreamCreateWithFlags(&side, cudaStreamNonBlocking);
        cudaEventCreateWithFlags(&ev_fork, cudaEventDisableTiming);
        cudaEventCreateWithFlags(&ev_ln,   cudaEventDisableTiming);
        cudaEventCreateWithFlags(&ev_side, cudaEventDisableTiming);
    }

    cudaEventRecord(ev_fork, 0);
    cudaStreamWaitEvent(side, ev_fork, 0);

    // side: tf32 weight packs + out init, then (after LN) f1h -> w_mo
    splitT_tf32<<<dim3(F / 32, D / 32), dim3(32, 8), 0, side>>>(w_in, wint, D, F, D);
    splitT_tf32<<<dim3(D / 32, F / 32), dim3(32, 8), 0, side>>>(w_mo, wmot, F, D, F);
    splitT_tf32<<<dim3(D / 32, D / 32), dim3(32, 8), 0, side>>>(w_ao, waot, D, D, D);
    init_out_kernel<<<(S * D / 4) / 256, 256, 0, side>>>(x, b_mo, b_ao, out);

    // main: qkv weight packs, LN (records ev_ln)
    splitT_kernel<<<dim3(D / 32, D / 32), dim3(32, 8)>>>(wq, wqkvh, wqkvl, D, D, D);
    splitT_kernel<<<dim3(D / 32, D / 32), dim3(32, 8)>>>(wk, wqkvh + (size_t)D * D, wqkvl + (size_t)D * D, D, D, D);
    splitT_kernel<<<dim3(D / 32, D / 32), dim3(32, 8)>>>(wv, wqkvh + (size_t)2 * D * D, wqkvl + (size_t)2 * D * D, D, D, D);
    ln_split_kernel<<<S, 256>>>(x, ln_scale, ln_bias, (uint32_t*)xnh, (uint32_t*)xnl, xnt);
    cudaEventRecord(ev_ln, 0);

    // side: h = gelu(xn @ w_in) [tf32], then out += h @ w_mo [tf32]
    cudaStreamWaitEvent(side, ev_ln, 0);
    tf32_gemm_h<<<dim3(F / GBN, S / GBM), 256, TF_SMEM, side>>>(xnt, wint, b_in, ht);
    tf32_gemm_acc<<<dim3(D / GBN, S / GBM), 256, TF_SMEM, side>>>(ht, wmot, out, D, F, F, F);
    cudaEventRecord(ev_side, side);

    // main: qkv GEMM (bf16 3-term), qk-norm, V tf32 transpose, attention
    hmma_gemm_qkv<<<dim3(N3 / GBN, S / GBM), 256, GSMEM>>>(
        xnh, xnl, wqkvh, wqkvl, bq, bk, bv, q, k, v);
    qknorm_split2<<<(2 * S * H) / 256, 256>>>(q, k, qn, kn,
                                              (uint32_t*)qsh, (uint32_t*)qsl,
                                              (uint32_t*)ksh, (uint32_t*)ksl);
    splitT_tf32<<<dim3(D / 32, S / 32), dim3(32, 8)>>>(v, vtt, S, D, S);
    hmma_attn<<<dim3(S / 128, H), 256, AT_SMEM>>>(qsh, qsl, ksh, ksl, vtt, ot);

    // join, then out += o @ w_ao (tf32 1-term) — FIX: launch with TF_SMEM (matches attribute)
    cudaStreamWaitEvent(0, ev_side, 0);
    tf32_gemm_acc<<<dim3(D / GBN, S / GBM), 256, TF_SMEM>>>(ot, waot, out, D, D, D, D);
}